// round 15
// baseline (speedup 1.0000x reference)
#include <cuda_runtime.h>
#include <cuda_bf16.h>
#include <cmath>
#include <cstdint>

namespace {

constexpr int BB = 2, NSEQ = 2048, DIM = 512, NH = 4, DH = 128, HID = 512;
constexpr int CHK = 64, NC = 32, BH = BB * NH, BN = BB * NSEQ;
constexpr int MAT1 = DH * HID;
constexpr int SLOT = 64 * 68;   // 4352 floats per 64x68 fp32 tile

__device__ float g_S  [BN * DIM];
__device__ float g_SR [BN * DIM];
__device__ float g_K  [BH * NSEQ * DH];
__device__ float g_V  [BH * NSEQ * DH];
__device__ float g_Q  [BH * NSEQ * DH];
__device__ float g_LR [BH * NSEQ];
__device__ float g_GATE[BH * NSEQ];
__device__ float g_POOL[BB * NC * DIM];
__device__ float g_MOM[BH * NC];
__device__ float g_DEC[BH * NC];
__device__ float g_Z  [BH * NSEQ * HID];
__device__ float g_GE [BH * NSEQ * HID];
__device__ float g_HM [BH * NSEQ * DH];
__device__ float g_DHb[BH * NSEQ * DH];
__device__ float g_DZ [BH * NSEQ * HID];
__device__ float g_W2T[NH * HID * DH];
__device__ float g_G1 [(size_t)BH * NC * MAT1];
__device__ float g_G2 [(size_t)BH * NC * MAT1];
__device__ float g_R1 [(size_t)BH * NC * MAT1];
__device__ float g_R2 [(size_t)BH * NC * MAT1];
__device__ float g_SG [BH * NC * DH];
__device__ float g_RG [BH * NC * DH];
__device__ float g_O  [BN * DIM];

__device__ __forceinline__ float sigm(float x) { return 1.f / (1.f + expf(-x)); }
__device__ __forceinline__ float geluf(float x) {
    return 0.5f * x * (1.f + erff(x * 0.70710678118654752f));
}
__device__ __forceinline__ float dgeluf(float x) {
    return 0.5f * (1.f + erff(x * 0.70710678118654752f))
         + x * 0.3989422804014327f * expf(-0.5f * x * x);
}
__device__ __forceinline__ void mmabf(float* c, const uint32_t* a, const uint32_t* b) {
    asm volatile("mma.sync.aligned.m16n8k16.row.col.f32.bf16.bf16.f32 "
                 "{%0,%1,%2,%3},{%4,%5,%6,%7},{%8,%9},{%0,%1,%2,%3};"
                 : "+f"(c[0]), "+f"(c[1]), "+f"(c[2]), "+f"(c[3])
                 : "r"(a[0]), "r"(a[1]), "r"(a[2]), "r"(a[3]), "r"(b[0]), "r"(b[1]));
}
__device__ __forceinline__ void mmatf(float* c, const uint32_t* a, const uint32_t* b) {
    asm volatile("mma.sync.aligned.m16n8k8.row.col.f32.tf32.tf32.f32 "
                 "{%0,%1,%2,%3},{%4,%5,%6,%7},{%8,%9},{%0,%1,%2,%3};"
                 : "+f"(c[0]), "+f"(c[1]), "+f"(c[2]), "+f"(c[3])
                 : "r"(a[0]), "r"(a[1]), "r"(a[2]), "r"(a[3]), "r"(b[0]), "r"(b[1]));
}
__device__ __forceinline__ void tf32split(float x, uint32_t& hi, uint32_t& lo) {
    asm("cvt.rna.tf32.f32 %0, %1;" : "=r"(hi) : "f"(x));
    float h = __uint_as_float(hi);
    asm("cvt.rna.tf32.f32 %0, %1;" : "=r"(lo) : "f"(x - h));
}

// -------------------- rmsnorm of seq with both gains -----------------------
__global__ void k_rmsnorm(const float* __restrict__ seq, const float* __restrict__ sg,
                          const float* __restrict__ rg) {
    int row = blockIdx.x, tid = threadIdx.x;
    const float* x = seq + (size_t)row * DIM;
    float v[4]; float ss = 0.f;
#pragma unroll
    for (int i = 0; i < 4; i++) { v[i] = x[tid + i * 128]; ss += v[i] * v[i]; }
    __shared__ float red[4];
#pragma unroll
    for (int o = 16; o; o >>= 1) ss += __shfl_xor_sync(~0u, ss, o);
    if ((tid & 31) == 0) red[tid >> 5] = ss;
    __syncthreads();
    float r = rsqrtf((red[0] + red[1] + red[2] + red[3]) * (1.f / DIM) + 1e-6f);
#pragma unroll
    for (int i = 0; i < 4; i++) {
        int d = tid + i * 128; float y = v[i] * r;
        g_S [(size_t)row * DIM + d] = y * sg[d];
        g_SR[(size_t)row * DIM + d] = y * rg[d];
    }
}

__global__ void k_pool() {
    int idx = blockIdx.x * blockDim.x + threadIdx.x;
    if (idx >= BB * NC * DIM) return;
    int d = idx % DIM; int bc = idx / DIM;
    size_t base = ((size_t)((bc / NC) * NSEQ + (bc % NC) * CHK)) * DIM + d;
    float a = 0.f;
#pragma unroll 4
    for (int t = 0; t < CHK; t++) a += g_S[base + (size_t)t * DIM];
    g_POOL[idx] = a * (1.f / CHK);
}

__global__ void k_lrgate(const float* __restrict__ Wlr, const float* __restrict__ blr,
                         const float* __restrict__ Wg) {
    int row = blockIdx.x, tid = threadIdx.x;
    float aL[4] = {0,0,0,0}, aG[4] = {0,0,0,0};
    for (int d = tid; d < DIM; d += 128) {
        float sv = g_S[(size_t)row * DIM + d], rv = g_SR[(size_t)row * DIM + d];
#pragma unroll
        for (int h = 0; h < 4; h++) { aL[h] += sv * Wlr[d*4+h]; aG[h] += rv * Wg[d*4+h]; }
    }
    __shared__ float red[32];
#pragma unroll
    for (int h = 0; h < 4; h++) {
        float a = aL[h], g = aG[h];
#pragma unroll
        for (int o = 16; o; o >>= 1) { a += __shfl_xor_sync(~0u, a, o); g += __shfl_xor_sync(~0u, g, o); }
        if ((tid & 31) == 0) { red[h*4 + (tid>>5)] = a; red[16 + h*4 + (tid>>5)] = g; }
    }
    __syncthreads();
    if (tid < 8) {
        int h = tid & 3; bool isG = tid >= 4;
        int base = (isG ? 16 : 0) + h * 4;
        float s = red[base] + red[base+1] + red[base+2] + red[base+3];
        int b = row / NSEQ, tk = row % NSEQ;
        if (!isG) g_LR  [(size_t)(b*NH + h) * NSEQ + tk] = sigm(s + blr[h]);
        else      g_GATE[(size_t)(b*NH + h) * NSEQ + tk] = sigm(s);
    }
}

__global__ void k_momdec(const float* __restrict__ Wm, const float* __restrict__ bm,
                         const float* __restrict__ Wd, const float* __restrict__ bd) {
    int row = blockIdx.x, tid = threadIdx.x;
    float am[4] = {0,0,0,0}, ad[4] = {0,0,0,0};
    for (int d = tid; d < DIM; d += 128) {
        float p = g_POOL[(size_t)row * DIM + d];
#pragma unroll
        for (int h = 0; h < 4; h++) { am[h] += p * Wm[d*4+h]; ad[h] += p * Wd[d*4+h]; }
    }
    __shared__ float red[32];
#pragma unroll
    for (int h = 0; h < 4; h++) {
        float a = am[h], g = ad[h];
#pragma unroll
        for (int o = 16; o; o >>= 1) { a += __shfl_xor_sync(~0u, a, o); g += __shfl_xor_sync(~0u, g, o); }
        if ((tid & 31) == 0) { red[h*4 + (tid>>5)] = a; red[16 + h*4 + (tid>>5)] = g; }
    }
    __syncthreads();
    if (tid < 8) {
        int h = tid & 3; bool isD = tid >= 4;
        int base = (isD ? 16 : 0) + h * 4;
        float s = red[base] + red[base+1] + red[base+2] + red[base+3];
        int b = row / NC, c = row % NC;
        if (!isD) g_MOM[(size_t)(b*NH + h) * NC + c] = sigm(s + bm[h]);
        else      g_DEC[(size_t)(b*NH + h) * NC + c] = sigm(s + bd[h]);
    }
}

__global__ void k_w2t(const float* __restrict__ mw2) {
    int idx = blockIdx.x * blockDim.x + threadIdx.x;
    if (idx >= NH * HID * DH) return;
    int h = idx >> 16, k = (idx & 65535) >> 9, n = idx & 511;
    g_W2T[idx] = mw2[(size_t)h * 65536 + (size_t)n * 128 + k];
}

// ---------- tensor-core GEMM, bf16 hi/lo split. Tile 64x64, BK=32, 128 thr --
__global__ void __launch_bounds__(128) k_tgemm(
        const float* __restrict__ A, const float* __restrict__ B,
        float* __restrict__ C, float* __restrict__ C2, const float* __restrict__ Zs,
        int K, int lda, int ldb, int ldc,
        unsigned long long aB, unsigned long long bB, unsigned long long cB,
        int bPerHead, int mode) {
    __shared__ __nv_bfloat16 Ah[64 * 40], Al[64 * 40], Bh[64 * 40], Bl[64 * 40];
    int bz = blockIdx.z;
    const float* Ab = A + (size_t)bz * aB;
    const float* Bb = B + (size_t)(bPerHead ? (bz % NH) : bz) * bB;
    float* Cb = C + (size_t)bz * cB;
    float* C2b = C2 ? C2 + (size_t)bz * cB : nullptr;
    const float* Zb = Zs ? Zs + (size_t)bz * cB : nullptr;
    int m0 = blockIdx.x * 64, n0 = blockIdx.y * 64;
    int tid = threadIdx.x, lane = tid & 31, warp = tid >> 5;
    int wm = warp >> 1, wn = warp & 1, gid = lane >> 2, tig = lane & 3;
    float acc[2][4][4] = {};

    for (int kt = 0; kt < K; kt += 32) {
#pragma unroll
        for (int p = 0; p < 4; p++) {
            int q = tid + p * 128; int r = q >> 3, c4 = (q & 7) * 4;
            float4 v = *(const float4*)&Ab[(size_t)(m0 + r) * lda + kt + c4];
            float vv[4] = {v.x, v.y, v.z, v.w};
#pragma unroll
            for (int i = 0; i < 4; i++) {
                __nv_bfloat16 h = __float2bfloat16(vv[i]);
                Ah[r * 40 + c4 + i] = h;
                Al[r * 40 + c4 + i] = __float2bfloat16(vv[i] - __bfloat162float(h));
            }
        }
#pragma unroll
        for (int p = 0; p < 4; p++) {
            int q = tid + p * 128; int r = q >> 4, c4 = (q & 15) * 4;
            float4 v = *(const float4*)&Bb[(size_t)(kt + r) * ldb + n0 + c4];
            float vv[4] = {v.x, v.y, v.z, v.w};
#pragma unroll
            for (int i = 0; i < 4; i++) {
                __nv_bfloat16 h = __float2bfloat16(vv[i]);
                Bh[(c4 + i) * 40 + r] = h;
                Bl[(c4 + i) * 40 + r] = __float2bfloat16(vv[i] - __bfloat162float(h));
            }
        }
        __syncthreads();
#pragma unroll
        for (int ks = 0; ks < 2; ks++) {
            int kb = ks * 16 + 2 * tig;
            uint32_t ah[2][4], al[2][4], bh[4][2], bl[4][2];
#pragma unroll
            for (int mf = 0; mf < 2; mf++) {
                int row = wm * 32 + mf * 16 + gid;
                ah[mf][0] = *(uint32_t*)&Ah[row * 40 + kb];
                ah[mf][1] = *(uint32_t*)&Ah[(row + 8) * 40 + kb];
                ah[mf][2] = *(uint32_t*)&Ah[row * 40 + kb + 8];
                ah[mf][3] = *(uint32_t*)&Ah[(row + 8) * 40 + kb + 8];
                al[mf][0] = *(uint32_t*)&Al[row * 40 + kb];
                al[mf][1] = *(uint32_t*)&Al[(row + 8) * 40 + kb];
                al[mf][2] = *(uint32_t*)&Al[row * 40 + kb + 8];
                al[mf][3] = *(uint32_t*)&Al[(row + 8) * 40 + kb + 8];
            }
#pragma unroll
            for (int nf = 0; nf < 4; nf++) {
                int n = wn * 32 + nf * 8 + gid;
                bh[nf][0] = *(uint32_t*)&Bh[n * 40 + kb];
                bh[nf][1] = *(uint32_t*)&Bh[n * 40 + kb + 8];
                bl[nf][0] = *(uint32_t*)&Bl[n * 40 + kb];
                bl[nf][1] = *(uint32_t*)&Bl[n * 40 + kb + 8];
            }
#pragma unroll
            for (int mf = 0; mf < 2; mf++)
#pragma unroll
                for (int nf = 0; nf < 4; nf++) {
                    mmabf(acc[mf][nf], ah[mf], bh[nf]);
                    mmabf(acc[mf][nf], ah[mf], bl[nf]);
                    mmabf(acc[mf][nf], al[mf], bh[nf]);
                }
        }
        __syncthreads();
    }
#pragma unroll
    for (int mf = 0; mf < 2; mf++)
#pragma unroll
        for (int nf = 0; nf < 4; nf++)
#pragma unroll
            for (int half = 0; half < 2; half++) {
                int row = m0 + wm * 32 + mf * 16 + gid + half * 8;
                int col = n0 + wn * 32 + nf * 8 + 2 * tig;
                float v0 = acc[mf][nf][half * 2], v1 = acc[mf][nf][half * 2 + 1];
                if (mode == 0) {
                    *(float2*)&Cb[(size_t)row * ldc + col] = make_float2(v0, v1);
                } else if (mode == 1) {
                    int b = row >> 11, tk = row & 2047, h = col >> 7, dh = col & 127;
                    *(float2*)&Cb[((size_t)(b * NH + h) * NSEQ + tk) * DH + dh] =
                        make_float2(v0, v1);
                } else if (mode == 2) {
                    size_t o = (size_t)row * ldc + col;
                    *(float2*)&Cb[o]  = make_float2(v0, v1);
                    *(float2*)&C2b[o] = make_float2(geluf(v0), geluf(v1));
                } else {
                    size_t o = (size_t)row * ldc + col;
                    float2 z = *(const float2*)&Zb[o];
                    *(float2*)&Cb[o] = make_float2(v0 * dgeluf(z.x), v1 * dgeluf(z.y));
                }
            }
}

// ---- rmsnorm-backward per chunk token; also -dgamma ------------------------
__global__ void k_backelem(const float* __restrict__ mgamma) {
    int chunk = blockIdx.x;
    int bh = chunk / NC, c = chunk % NC, h = bh % NH;
    int tid = threadIdx.x;
    float gd = mgamma[h * DH + tid];
    __shared__ float red[4];
    float dg = 0.f;
    size_t rowBase = ((size_t)bh * NSEQ + c * CHK) * DH;
    for (int t = 0; t < CHK; t++) {
        size_t off = rowBase + (size_t)t * DH + tid;
        float hv = g_HM[off];
        float ss = hv * hv;
#pragma unroll
        for (int o = 16; o; o >>= 1) ss += __shfl_xor_sync(~0u, ss, o);
        if ((tid & 31) == 0) red[tid >> 5] = ss;
        __syncthreads();
        float tot = red[0] + red[1] + red[2] + red[3];
        __syncthreads();
        float r = rsqrtf(tot * (1.f / DH) + 1e-6f);
        float y = hv * r;
        float lr = g_LR[(size_t)bh * NSEQ + c * CHK + t];
        float dp = (2.f / DH) * (y * gd + g_K[off] - g_V[off]) * lr;
        dg += dp * y;
        float dy = dp * gd;
        float dd = dy * hv;
#pragma unroll
        for (int o = 16; o; o >>= 1) dd += __shfl_xor_sync(~0u, dd, o);
        if ((tid & 31) == 0) red[tid >> 5] = dd;
        __syncthreads();
        float dot = red[0] + red[1] + red[2] + red[3];
        __syncthreads();
        g_DHb[off] = r * dy - (r * r * r * (1.f / DH)) * hv * dot;
    }
    g_SG[(size_t)chunk * DH + tid] = -dg;
}

// ---- generic tf32-split 64x64 TC matmul on fp32 smem -----------------------
// C[64x68] = scl*op(A)@op(B) (+ascl*add). op via index swap: TRA: A-op=storage^T.
// TRB: B-op (kxn) = Y^T (x = Y[n*ldb+k]); else x = Y[k*ldb+n].
template<bool TRA, bool TRB>
__device__ __forceinline__ void mmt(const float* __restrict__ A, int lda, int aOff,
                                    const float* __restrict__ B, int ldb,
                                    float* __restrict__ C, float scl,
                                    const float* __restrict__ add, float ascl,
                                    int K, int tid) {
    int lane = tid & 31, warp = tid >> 5;
    int wm = warp >> 1, wn = warp & 1, gid = lane >> 2, tig = lane & 3;
    __syncthreads();
    float acc[4][4] = {};
    for (int k0 = 0; k0 < K; k0 += 8) {
        uint32_t ah[4], al[4];
#pragma unroll
        for (int r = 0; r < 4; r++) {
            int mm = wm * 16 + gid + (r & 1) * 8;
            int kk = k0 + tig + (r >> 1) * 4;
            float x = TRA ? A[kk * lda + aOff + mm] : A[(aOff + mm) * lda + kk];
            tf32split(x, ah[r], al[r]);
        }
#pragma unroll
        for (int ns = 0; ns < 4; ns++) {
            uint32_t bh[2], bl[2];
            int nc = wn * 32 + ns * 8 + gid;
#pragma unroll
            for (int r = 0; r < 2; r++) {
                int kk = k0 + tig + r * 4;
                float x = TRB ? B[nc * ldb + kk] : B[kk * ldb + nc];
                tf32split(x, bh[r], bl[r]);
            }
            mmatf(acc[ns], ah, bh);
            mmatf(acc[ns], ah, bl);
            mmatf(acc[ns], al, bh);
        }
    }
#pragma unroll
    for (int ns = 0; ns < 4; ns++) {
        int nc = wn * 32 + ns * 8 + 2 * tig;
#pragma unroll
        for (int h = 0; h < 2; h++) {
            int row = wm * 16 + gid + h * 8;
            float v0 = scl * acc[ns][h * 2];
            float v1 = scl * acc[ns][h * 2 + 1];
            if (add) {
                v0 += ascl * add[row * 68 + nc];
                v1 += ascl * add[row * 68 + nc + 1];
            }
            C[row * 68 + nc] = v0;
            C[row * 68 + nc + 1] = v1;
        }
    }
}

// ---- Gram-space NS, full tensor-core (tf32 split). 104.4KB smem, 256 thr ---
__global__ void __launch_bounds__(256) k_nsg() {
    extern __shared__ float sm[];
    float* P  = sm;             float* Q = sm + SLOT;
    float* Mb = sm + 2 * SLOT;  float* F = sm + 3 * SLOT;
    float* G  = sm + 4 * SLOT;  float* W = sm + 5 * SLOT;
    __shared__ float red[9];
    int mat = blockIdx.x;
    bool w2 = mat >= 256;
    int ch = w2 ? mat - 256 : mat;
    size_t rowBase = (size_t)(ch / NC) * NSEQ + (size_t)(ch % NC) * CHK;
    const float* Ag = (w2 ? g_DHb : g_K) + rowBase * DH;
    const float* Bg = (w2 ? g_GE : g_DZ) + rowBase * HID;
    float* Gout = (w2 ? g_G2 : g_G1) + (size_t)ch * MAT1;
    int tid = threadIdx.x;
    float* As = F;   // A [t][i], stride 132, spans F+G (8448 <= 8704 floats)

#pragma unroll
    for (int p = 0; p < 32; p++) { int idx = tid + p * 256;
        As[(idx >> 7) * 132 + (idx & 127)] = Ag[idx]; }
    // P = A A^T  (A-op nt; B-op = A^T -> TRB index = A[t][i])
    mmt<false, true>(As, 132, 0, As, 132, P, 1.f, nullptr, 0.f, 128, tid);
    // Q = B B^T accumulated over 8 panels staged in W [u][jl]
    for (int p = 0; p < 8; p++) {
        __syncthreads();
#pragma unroll
        for (int q = 0; q < 16; q++) { int idx = tid + q * 256; int u = idx >> 6, jl = idx & 63;
            W[u * 68 + jl] = Bg[(size_t)u * HID + p * 64 + jl]; }
        mmt<false, true>(W, 68, 0, W, 68, Q, 1.f, p ? Q : nullptr, 1.f, 64, tid);
    }
    __syncthreads();
    {   // 1/||t||_F = rsqrt(tr(PQ))
        float tsum = 0.f;
#pragma unroll
        for (int q = 0; q < 16; q++) { int idx = tid + q * 256; int t = idx >> 6, u = idx & 63;
            tsum += P[t * 68 + u] * Q[t * 68 + u]; }
#pragma unroll
        for (int o = 16; o; o >>= 1) tsum += __shfl_xor_sync(~0u, tsum, o);
        if ((tid & 31) == 0) red[tid >> 5] = tsum;
        __syncthreads();
        if (tid == 0) {
            float tot = 0.f;
#pragma unroll
            for (int i = 0; i < 8; i++) tot += red[i];
            red[8] = 1.f / fmaxf(sqrtf(tot), 1e-7f);
        }
        __syncthreads();
    }
    float s = red[8];
#pragma unroll
    for (int q = 0; q < 16; q++) { int idx = tid + q * 256; int t = idx >> 6, u = idx & 63;
        Mb[t * 68 + u] = (t == u) ? -s : 0.f; }

    const float ca = 3.4445f, cb = -4.775f, cc = 2.0315f;
    float *pM = Mb, *pW = W;
#pragma unroll 1
    for (int it = 0; it < 5; it++) {
        mmt<false, false>(P,  68, 0, pM, 68, F,  1.f, nullptr, 0.f, 64, tid); // X1 = P M
        mmt<true , false>(pM, 68, 0, F,  68, G,  1.f, nullptr, 0.f, 64, tid); // T2 = M^T X1
        mmt<false, false>(Q,  68, 0, G,  68, F,  1.f, nullptr, 0.f, 64, tid); // F = Q T2
        mmt<false, false>(F,  68, 0, F,  68, G,  cc,  F,  cb,  64, tid);      // G = cF^2+bF
        mmt<false, false>(pM, 68, 0, G,  68, pW, 1.f, pM, ca,  64, tid);      // M' = M G+aM
        float* tmp = pM; pM = pW; pW = tmp;                                    // final -> W
    }
    __syncthreads();
#pragma unroll
    for (int p = 0; p < 32; p++) { int idx = tid + p * 256;
        As[(idx >> 7) * 132 + (idx & 127)] = Ag[idx]; }
    // R = A^T M (128x64) in two halves -> P, Q
    mmt<true, false>(As, 132, 0,  pM, 68, P, 1.f, nullptr, 0.f, 64, tid);
    mmt<true, false>(As, 132, 64, pM, 68, Q, 1.f, nullptr, 0.f, 64, tid);
    // out = R @ B, 8 panels staged in Mb; result tile in F; copy to global
    float* Rh[2] = {P, Q};
    for (int p = 0; p < 8; p++) {
        __syncthreads();
#pragma unroll
        for (int q = 0; q < 16; q++) { int idx = tid + q * 256; int u = idx >> 6, jl = idx & 63;
            Mb[u * 68 + jl] = Bg[(size_t)u * HID + p * 64 + jl]; }
        for (int hf = 0; hf < 2; hf++) {
            mmt<false, false>(Rh[hf], 68, 0, Mb, 68, F, 1.f, nullptr, 0.f, 64, tid);
            __syncthreads();
            if (!w2) {
#pragma unroll
                for (int q = 0; q < 16; q++) { int idx = tid + q * 256; int r = idx >> 6, c = idx & 63;
                    Gout[(size_t)(hf * 64 + r) * HID + p * 64 + c] = F[r * 68 + c]; }
            } else {
#pragma unroll
                for (int q = 0; q < 16; q++) { int idx = tid + q * 256; int c = idx >> 6, r = idx & 63;
                    Gout[(size_t)(p * 64 + c) * DH + hf * 64 + r] = F[r * 68 + c]; }
            }
        }
    }
}

__global__ void k_scan(const float* __restrict__ S, const float* __restrict__ init,
                       float* __restrict__ R, int matSize) {
    size_t e = (size_t)blockIdx.x * blockDim.x + threadIdx.x;
    if (e >= (size_t)BH * matSize) return;
    int bh = (int)(e / matSize); size_t off = e % matSize;
    float m = 0.f, w = init[(size_t)(bh % NH) * matSize + off];
    const float* mom = g_MOM + (size_t)bh * NC;
    const float* dec = g_DEC + (size_t)bh * NC;
    for (int c = 0; c < NC; c++) {
        size_t idx = ((size_t)bh * NC + c) * matSize + off;
        m = mom[c] * m + S[idx];
        R[idx] = w;
        w = (1.f - dec[c]) * w + m;
    }
}

// ---- fused per-chunk retrieval: gelu-MLP + rmsnorm + residual + gate -------
__global__ void __launch_bounds__(256) k_retrieve() {
    extern __shared__ float sm[];
    float* qS  = sm;
    float* Z2S = sm + 128 * 65;
    float* buf = sm + 128 * 65 + 512 * 65;
    int chunk = blockIdx.x;
    int bh = chunk / NC, c = chunk % NC;
    int tid = threadIdx.x, tx = tid & 15, ty = tid >> 4;
    const float* Qp = g_Q + ((size_t)bh * NSEQ + c * CHK) * DH;
    const float* R1 = g_R1 + (size_t)chunk * MAT1;
    const float* R2 = g_R2 + (size_t)chunk * MAT1;
#pragma unroll
    for (int p = 0; p < 32; p++) { int idx = tid + p * 256; int d = idx & 127, t = idx >> 7;
        qS[d * 65 + t] = Qp[(size_t)t * DH + d]; }
    __syncthreads();
    for (int j0 = 0; j0 < 512; j0 += 64) {
#pragma unroll
        for (int p = 0; p < 32; p++) { int idx = tid + p * 256; int jj = idx & 63, d = idx >> 6;
            buf[d * 65 + jj] = R1[(size_t)d * 512 + j0 + jj]; }
        __syncthreads();
        float acc[4][4] = {};
#pragma unroll 4
        for (int d = 0; d < 128; d++) {
            float a[4], b[4];
#pragma unroll
            for (int ii = 0; ii < 4; ii++) a[ii] = qS[d * 65 + tx + 16 * ii];
#pragma unroll
            for (int cc = 0; cc < 4; cc++) b[cc] = buf[d * 65 + ty * 4 + cc];
#pragma unroll
            for (int ii = 0; ii < 4; ii++)
#pragma unroll
                for (int cc = 0; cc < 4; cc++) acc[ii][cc] += a[ii] * b[cc];
        }
#pragma unroll
        for (int ii = 0; ii < 4; ii++)
#pragma unroll
            for (int cc = 0; cc < 4; cc++)
                Z2S[(j0 + ty * 4 + cc) * 65 + tx + 16 * ii] = geluf(acc[ii][cc]);
        __syncthreads();
    }
    float acr[4][8] = {};
    for (int j0 = 0; j0 < 512; j0 += 64) {
#pragma unroll
        for (int p = 0; p < 32; p++) { int idx = tid + p * 256; int dd = idx & 127, jj = idx >> 7;
            buf[jj * 130 + dd] = R2[(size_t)(j0 + jj) * 128 + dd]; }
        __syncthreads();
#pragma unroll 2
        for (int jj = 0; jj < 64; jj++) {
            float a[4], bb[8];
#pragma unroll
            for (int ii = 0; ii < 4; ii++) a[ii] = Z2S[(j0 + jj) * 65 + tx + 16 * ii];
#pragma unroll
            for (int cc = 0; cc < 8; cc++) bb[cc] = buf[jj * 130 + ty * 8 + cc];
#pragma unroll
            for (int ii = 0; ii < 4; ii++)
#pragma unroll
                for (int cc = 0; cc < 8; cc++) acr[ii][cc] += a[ii] * bb[cc];
        }
        __syncthreads();
    }
#pragma unroll
    for (int ii = 0; ii < 4; ii++)
#pragma unroll
        for (int cc = 0; cc < 8; cc++)
            buf[(tx + 16 * ii) * 130 + ty * 8 + cc] = acr[ii][cc];
    __syncthreads();
    int grp = tid & 3, tok = tid >> 2;
    const float* rgam = g_RG + (size_t)chunk * DH;
    float ssv = 0.f;
#pragma unroll
    for (int k = 0; k < 32; k++) { float v = buf[tok * 130 + grp * 32 + k]; ssv += v * v; }
    ssv += __shfl_xor_sync(~0u, ssv, 1);
    ssv += __shfl_xor_sync(~0u, ssv, 2);
    float r = rsqrtf(ssv * (1.f / 128.f) + 1e-6f);
    int b = bh / NH, h = bh % NH;
    float gate = g_GATE[(size_t)bh * NSEQ + c * CHK + tok];
    size_t obase = ((size_t)b * NSEQ + c * CHK + tok) * 512 + h * 128;
#pragma unroll
    for (int k = 0; k < 32; k++) {
        int dd = grp * 32 + k;
        float v = buf[tok * 130 + dd] * r * rgam[dd] + qS[dd * 65 + tok];
        g_O[obase + dd] = v * gate;
    }
}

} // namespace

extern "C" void kernel_launch(void* const* d_in, const int* in_sizes, int n_in,
                              void* d_out, int out_size) {
    const float* seq   = (const float*)d_in[0];
    const float* sg    = (const float*)d_in[1];
    const float* rg    = (const float*)d_in[2];
    const float* Wq    = (const float*)d_in[3];
    const float* Wk    = (const float*)d_in[4];
    const float* Wv    = (const float*)d_in[5];
    const float* Wlr   = (const float*)d_in[6];
    const float* blr   = (const float*)d_in[7];
    const float* Wm    = (const float*)d_in[8];
    const float* bm    = (const float*)d_in[9];
    const float* Wd    = (const float*)d_in[10];
    const float* bd    = (const float*)d_in[11];
    const float* Wgate = (const float*)d_in[12];
    const float* Wc    = (const float*)d_in[13];
    const float* mw1   = (const float*)d_in[14];
    const float* mw2   = (const float*)d_in[15];
    const float* mgam  = (const float*)d_in[16];
    float* out = (float*)d_out;

    const int NSG_SMEM = 6 * SLOT * 4;                            // 104,448 B
    const int RET_SMEM = (128 * 65 + 512 * 65 + 128 * 65) * 4;    // 199,680 B
    cudaFuncSetAttribute(k_nsg, cudaFuncAttributeMaxDynamicSharedMemorySize, NSG_SMEM);
    cudaFuncSetAttribute(k_retrieve, cudaFuncAttributeMaxDynamicSharedMemorySize, RET_SMEM);

    float *pG1, *pG2, *pR1, *pR2, *pSG, *pRG, *pK, *pGE, *pDZ, *pDHb;
    float *pS, *pSR, *pO, *pV, *pQ, *pZ, *pHM, *pW2T;
    cudaGetSymbolAddress((void**)&pG1, g_G1);
    cudaGetSymbolAddress((void**)&pG2, g_G2);
    cudaGetSymbolAddress((void**)&pR1, g_R1);
    cudaGetSymbolAddress((void**)&pR2, g_R2);
    cudaGetSymbolAddress((void**)&pSG, g_SG);
    cudaGetSymbolAddress((void**)&pRG, g_RG);
    cudaGetSymbolAddress((void**)&pK,  g_K);
    cudaGetSymbolAddress((void**)&pGE, g_GE);
    cudaGetSymbolAddress((void**)&pDZ, g_DZ);
    cudaGetSymbolAddress((void**)&pDHb,g_DHb);
    cudaGetSymbolAddress((void**)&pS,  g_S);
    cudaGetSymbolAddress((void**)&pSR, g_SR);
    cudaGetSymbolAddress((void**)&pO,  g_O);
    cudaGetSymbolAddress((void**)&pV,  g_V);
    cudaGetSymbolAddress((void**)&pQ,  g_Q);
    cudaGetSymbolAddress((void**)&pZ,  g_Z);
    cudaGetSymbolAddress((void**)&pHM, g_HM);
    cudaGetSymbolAddress((void**)&pW2T,g_W2T);

    k_rmsnorm<<<BN, 128>>>(seq, sg, rg);
    k_pool<<<(BB * NC * DIM + 255) / 256, 256>>>();
    k_lrgate<<<BN, 128>>>(Wlr, blr, Wgate);
    k_momdec<<<BB * NC, 128>>>(Wm, bm, Wd, bd);
    k_w2t<<<(NH * HID * DH + 255) / 256, 256>>>(mw2);

    unsigned long long ND = (unsigned long long)NSEQ * DH;
    unsigned long long NHd = (unsigned long long)NSEQ * HID;
    dim3 gp(64, 8, 1);
    k_tgemm<<<gp, 128>>>(pS,  Wk, pK, nullptr, nullptr, 512, 512, 512, 0, 0, 0, 0, 0, 1);
    k_tgemm<<<gp, 128>>>(pS,  Wv, pV, nullptr, nullptr, 512, 512, 512, 0, 0, 0, 0, 0, 1);
    k_tgemm<<<gp, 128>>>(pSR, Wq, pQ, nullptr, nullptr, 512, 512, 512, 0, 0, 0, 0, 0, 1);

    dim3 gz(32, 8, 8);
    k_tgemm<<<gz, 128>>>(pK, mw1, pZ, pGE, nullptr, 128, 128, 512, 512, ND, MAT1, NHd, 1, 2);
    dim3 gh(32, 2, 8);
    k_tgemm<<<gh, 128>>>(pGE, mw2, pHM, nullptr, nullptr, 512, 512, 128, 128, NHd, MAT1, ND, 1, 0);

    k_backelem<<<BH * NC, 128>>>(mgam);

    k_tgemm<<<gz, 128>>>(pDHb, pW2T, pDZ, nullptr, pZ, 128, 128, 512, 512,
                         ND, (unsigned long long)HID * DH, NHd, 1, 3);

    k_nsg<<<512, 256, NSG_SMEM>>>();

    k_scan<<<(BH * MAT1 + 255) / 256, 256>>>(pG1, mw1, pR1, MAT1);
    k_scan<<<(BH * MAT1 + 255) / 256, 256>>>(pG2, mw2, pR2, MAT1);
    k_scan<<<(BH * DH + 255) / 256, 256>>>(pSG, mgam, pRG, DH);

    k_retrieve<<<BH * NC, 256, RET_SMEM>>>();

    k_tgemm<<<gp, 128>>>(pO, Wc, out, nullptr, nullptr, 512, 512, 512, 512, 0, 0, 0, 0, 0);
}

// round 16
// speedup vs baseline: 1.4038x; 1.4038x over previous
#include <cuda_runtime.h>
#include <cuda_bf16.h>
#include <cmath>
#include <cstdint>

namespace {

constexpr int BB = 2, NSEQ = 2048, DIM = 512, NH = 4, DH = 128, HID = 512;
constexpr int CHK = 64, NC = 32, BH = BB * NH, BN = BB * NSEQ;
constexpr int MAT1 = DH * HID;
constexpr int SP = 65;
constexpr int NB = 64 * SP;

__device__ float g_S  [BN * DIM];
__device__ float g_SR [BN * DIM];
__device__ float g_K  [BH * NSEQ * DH];
__device__ float g_V  [BH * NSEQ * DH];
__device__ float g_Q  [BH * NSEQ * DH];
__device__ float g_LR [BH * NSEQ];
__device__ float g_GATE[BH * NSEQ];
__device__ float g_POOL[BB * NC * DIM];
__device__ float g_MOM[BH * NC];
__device__ float g_DEC[BH * NC];
__device__ float g_Z  [BH * NSEQ * HID];   // later reused as Z2 (retrieval hidden)
__device__ float g_GE [BH * NSEQ * HID];
__device__ float g_HM [BH * NSEQ * DH];    // later reused as retrieval MLP output
__device__ float g_DHb[BH * NSEQ * DH];
__device__ float g_DZ [BH * NSEQ * HID];
__device__ float g_W2T[NH * HID * DH];
__device__ float g_G1 [(size_t)BH * NC * MAT1];
__device__ float g_G2 [(size_t)BH * NC * MAT1];
__device__ float g_R1 [(size_t)BH * NC * MAT1];
__device__ float g_R2 [(size_t)BH * NC * MAT1];
__device__ float g_SG [BH * NC * DH];
__device__ float g_RG [BH * NC * DH];
__device__ float g_O  [BN * DIM];

__device__ __forceinline__ float sigm(float x) { return 1.f / (1.f + expf(-x)); }
__device__ __forceinline__ float geluf(float x) {
    return 0.5f * x * (1.f + erff(x * 0.70710678118654752f));
}
__device__ __forceinline__ float dgeluf(float x) {
    return 0.5f * (1.f + erff(x * 0.70710678118654752f))
         + x * 0.3989422804014327f * expf(-0.5f * x * x);
}
__device__ __forceinline__ void mmabf(float* c, const uint32_t* a, const uint32_t* b) {
    asm volatile("mma.sync.aligned.m16n8k16.row.col.f32.bf16.bf16.f32 "
                 "{%0,%1,%2,%3},{%4,%5,%6,%7},{%8,%9},{%0,%1,%2,%3};"
                 : "+f"(c[0]), "+f"(c[1]), "+f"(c[2]), "+f"(c[3])
                 : "r"(a[0]), "r"(a[1]), "r"(a[2]), "r"(a[3]), "r"(b[0]), "r"(b[1]));
}

// -------------------- rmsnorm of seq with both gains -----------------------
__global__ void k_rmsnorm(const float* __restrict__ seq, const float* __restrict__ sg,
                          const float* __restrict__ rg) {
    int row = blockIdx.x, tid = threadIdx.x;
    const float* x = seq + (size_t)row * DIM;
    float v[4]; float ss = 0.f;
#pragma unroll
    for (int i = 0; i < 4; i++) { v[i] = x[tid + i * 128]; ss += v[i] * v[i]; }
    __shared__ float red[4];
#pragma unroll
    for (int o = 16; o; o >>= 1) ss += __shfl_xor_sync(~0u, ss, o);
    if ((tid & 31) == 0) red[tid >> 5] = ss;
    __syncthreads();
    float r = rsqrtf((red[0] + red[1] + red[2] + red[3]) * (1.f / DIM) + 1e-6f);
#pragma unroll
    for (int i = 0; i < 4; i++) {
        int d = tid + i * 128; float y = v[i] * r;
        g_S [(size_t)row * DIM + d] = y * sg[d];
        g_SR[(size_t)row * DIM + d] = y * rg[d];
    }
}

__global__ void k_pool() {
    int idx = blockIdx.x * blockDim.x + threadIdx.x;
    if (idx >= BB * NC * DIM) return;
    int d = idx % DIM; int bc = idx / DIM;
    size_t base = ((size_t)((bc / NC) * NSEQ + (bc % NC) * CHK)) * DIM + d;
    float a = 0.f;
#pragma unroll 4
    for (int t = 0; t < CHK; t++) a += g_S[base + (size_t)t * DIM];
    g_POOL[idx] = a * (1.f / CHK);
}

__global__ void k_lrgate(const float* __restrict__ Wlr, const float* __restrict__ blr,
                         const float* __restrict__ Wg) {
    int row = blockIdx.x, tid = threadIdx.x;
    float aL[4] = {0,0,0,0}, aG[4] = {0,0,0,0};
    for (int d = tid; d < DIM; d += 128) {
        float sv = g_S[(size_t)row * DIM + d], rv = g_SR[(size_t)row * DIM + d];
#pragma unroll
        for (int h = 0; h < 4; h++) { aL[h] += sv * Wlr[d*4+h]; aG[h] += rv * Wg[d*4+h]; }
    }
    __shared__ float red[32];
#pragma unroll
    for (int h = 0; h < 4; h++) {
        float a = aL[h], g = aG[h];
#pragma unroll
        for (int o = 16; o; o >>= 1) { a += __shfl_xor_sync(~0u, a, o); g += __shfl_xor_sync(~0u, g, o); }
        if ((tid & 31) == 0) { red[h*4 + (tid>>5)] = a; red[16 + h*4 + (tid>>5)] = g; }
    }
    __syncthreads();
    if (tid < 8) {
        int h = tid & 3; bool isG = tid >= 4;
        int base = (isG ? 16 : 0) + h * 4;
        float s = red[base] + red[base+1] + red[base+2] + red[base+3];
        int b = row / NSEQ, tk = row % NSEQ;
        if (!isG) g_LR  [(size_t)(b*NH + h) * NSEQ + tk] = sigm(s + blr[h]);
        else      g_GATE[(size_t)(b*NH + h) * NSEQ + tk] = sigm(s);
    }
}

__global__ void k_momdec(const float* __restrict__ Wm, const float* __restrict__ bm,
                         const float* __restrict__ Wd, const float* __restrict__ bd) {
    int row = blockIdx.x, tid = threadIdx.x;
    float am[4] = {0,0,0,0}, ad[4] = {0,0,0,0};
    for (int d = tid; d < DIM; d += 128) {
        float p = g_POOL[(size_t)row * DIM + d];
#pragma unroll
        for (int h = 0; h < 4; h++) { am[h] += p * Wm[d*4+h]; ad[h] += p * Wd[d*4+h]; }
    }
    __shared__ float red[32];
#pragma unroll
    for (int h = 0; h < 4; h++) {
        float a = am[h], g = ad[h];
#pragma unroll
        for (int o = 16; o; o >>= 1) { a += __shfl_xor_sync(~0u, a, o); g += __shfl_xor_sync(~0u, g, o); }
        if ((tid & 31) == 0) { red[h*4 + (tid>>5)] = a; red[16 + h*4 + (tid>>5)] = g; }
    }
    __syncthreads();
    if (tid < 8) {
        int h = tid & 3; bool isD = tid >= 4;
        int base = (isD ? 16 : 0) + h * 4;
        float s = red[base] + red[base+1] + red[base+2] + red[base+3];
        int b = row / NC, c = row % NC;
        if (!isD) g_MOM[(size_t)(b*NH + h) * NC + c] = sigm(s + bm[h]);
        else      g_DEC[(size_t)(b*NH + h) * NC + c] = sigm(s + bd[h]);
    }
}

__global__ void k_w2t(const float* __restrict__ mw2) {
    int idx = blockIdx.x * blockDim.x + threadIdx.x;
    if (idx >= NH * HID * DH) return;
    int h = idx >> 16, k = (idx & 65535) >> 9, n = idx & 511;
    g_W2T[idx] = mw2[(size_t)h * 65536 + (size_t)n * 128 + k];
}

// ---------- tensor-core GEMM, bf16 hi/lo split. Tile 64x64, BK=32, 128 thr --
// modes: 0 plain; 1 head-scatter; 2 store Z + gelu(Z); 3 *dgelu(Zs); 4 gelu only.
__global__ void __launch_bounds__(128) k_tgemm(
        const float* __restrict__ A, const float* __restrict__ B,
        float* __restrict__ C, float* __restrict__ C2, const float* __restrict__ Zs,
        int K, int lda, int ldb, int ldc,
        unsigned long long aB, unsigned long long bB, unsigned long long cB,
        int bPerHead, int mode) {
    __shared__ __nv_bfloat16 Ah[64 * 40], Al[64 * 40], Bh[64 * 40], Bl[64 * 40];
    int bz = blockIdx.z;
    const float* Ab = A + (size_t)bz * aB;
    const float* Bb = B + (size_t)(bPerHead ? (bz % NH) : bz) * bB;
    float* Cb = C + (size_t)bz * cB;
    float* C2b = C2 ? C2 + (size_t)bz * cB : nullptr;
    const float* Zb = Zs ? Zs + (size_t)bz * cB : nullptr;
    int m0 = blockIdx.x * 64, n0 = blockIdx.y * 64;
    int tid = threadIdx.x, lane = tid & 31, warp = tid >> 5;
    int wm = warp >> 1, wn = warp & 1, gid = lane >> 2, tig = lane & 3;
    float acc[2][4][4] = {};

    for (int kt = 0; kt < K; kt += 32) {
#pragma unroll
        for (int p = 0; p < 4; p++) {
            int q = tid + p * 128; int r = q >> 3, c4 = (q & 7) * 4;
            float4 v = *(const float4*)&Ab[(size_t)(m0 + r) * lda + kt + c4];
            float vv[4] = {v.x, v.y, v.z, v.w};
#pragma unroll
            for (int i = 0; i < 4; i++) {
                __nv_bfloat16 h = __float2bfloat16(vv[i]);
                Ah[r * 40 + c4 + i] = h;
                Al[r * 40 + c4 + i] = __float2bfloat16(vv[i] - __bfloat162float(h));
            }
        }
#pragma unroll
        for (int p = 0; p < 4; p++) {
            int q = tid + p * 128; int r = q >> 4, c4 = (q & 15) * 4;
            float4 v = *(const float4*)&Bb[(size_t)(kt + r) * ldb + n0 + c4];
            float vv[4] = {v.x, v.y, v.z, v.w};
#pragma unroll
            for (int i = 0; i < 4; i++) {
                __nv_bfloat16 h = __float2bfloat16(vv[i]);
                Bh[(c4 + i) * 40 + r] = h;
                Bl[(c4 + i) * 40 + r] = __float2bfloat16(vv[i] - __bfloat162float(h));
            }
        }
        __syncthreads();
#pragma unroll
        for (int ks = 0; ks < 2; ks++) {
            int kb = ks * 16 + 2 * tig;
            uint32_t ah[2][4], al[2][4], bh[4][2], bl[4][2];
#pragma unroll
            for (int mf = 0; mf < 2; mf++) {
                int row = wm * 32 + mf * 16 + gid;
                ah[mf][0] = *(uint32_t*)&Ah[row * 40 + kb];
                ah[mf][1] = *(uint32_t*)&Ah[(row + 8) * 40 + kb];
                ah[mf][2] = *(uint32_t*)&Ah[row * 40 + kb + 8];
                ah[mf][3] = *(uint32_t*)&Ah[(row + 8) * 40 + kb + 8];
                al[mf][0] = *(uint32_t*)&Al[row * 40 + kb];
                al[mf][1] = *(uint32_t*)&Al[(row + 8) * 40 + kb];
                al[mf][2] = *(uint32_t*)&Al[row * 40 + kb + 8];
                al[mf][3] = *(uint32_t*)&Al[(row + 8) * 40 + kb + 8];
            }
#pragma unroll
            for (int nf = 0; nf < 4; nf++) {
                int n = wn * 32 + nf * 8 + gid;
                bh[nf][0] = *(uint32_t*)&Bh[n * 40 + kb];
                bh[nf][1] = *(uint32_t*)&Bh[n * 40 + kb + 8];
                bl[nf][0] = *(uint32_t*)&Bl[n * 40 + kb];
                bl[nf][1] = *(uint32_t*)&Bl[n * 40 + kb + 8];
            }
#pragma unroll
            for (int mf = 0; mf < 2; mf++)
#pragma unroll
                for (int nf = 0; nf < 4; nf++) {
                    mmabf(acc[mf][nf], ah[mf], bh[nf]);
                    mmabf(acc[mf][nf], ah[mf], bl[nf]);
                    mmabf(acc[mf][nf], al[mf], bh[nf]);
                }
        }
        __syncthreads();
    }
#pragma unroll
    for (int mf = 0; mf < 2; mf++)
#pragma unroll
        for (int nf = 0; nf < 4; nf++)
#pragma unroll
            for (int half = 0; half < 2; half++) {
                int row = m0 + wm * 32 + mf * 16 + gid + half * 8;
                int col = n0 + wn * 32 + nf * 8 + 2 * tig;
                float v0 = acc[mf][nf][half * 2], v1 = acc[mf][nf][half * 2 + 1];
                if (mode == 0) {
                    *(float2*)&Cb[(size_t)row * ldc + col] = make_float2(v0, v1);
                } else if (mode == 1) {
                    int b = row >> 11, tk = row & 2047, h = col >> 7, dh = col & 127;
                    *(float2*)&Cb[((size_t)(b * NH + h) * NSEQ + tk) * DH + dh] =
                        make_float2(v0, v1);
                } else if (mode == 2) {
                    size_t o = (size_t)row * ldc + col;
                    *(float2*)&Cb[o]  = make_float2(v0, v1);
                    *(float2*)&C2b[o] = make_float2(geluf(v0), geluf(v1));
                } else if (mode == 3) {
                    size_t o = (size_t)row * ldc + col;
                    float2 z = *(const float2*)&Zb[o];
                    *(float2*)&Cb[o] = make_float2(v0 * dgeluf(z.x), v1 * dgeluf(z.y));
                } else {
                    size_t o = (size_t)row * ldc + col;
                    *(float2*)&Cb[o] = make_float2(geluf(v0), geluf(v1));
                }
            }
}

// ---- rmsnorm-backward per chunk token; also -dgamma ------------------------
__global__ void k_backelem(const float* __restrict__ mgamma) {
    int chunk = blockIdx.x;
    int bh = chunk / NC, c = chunk % NC, h = bh % NH;
    int tid = threadIdx.x;
    float gd = mgamma[h * DH + tid];
    __shared__ float red[4];
    float dg = 0.f;
    size_t rowBase = ((size_t)bh * NSEQ + c * CHK) * DH;
    for (int t = 0; t < CHK; t++) {
        size_t off = rowBase + (size_t)t * DH + tid;
        float hv = g_HM[off];
        float ss = hv * hv;
#pragma unroll
        for (int o = 16; o; o >>= 1) ss += __shfl_xor_sync(~0u, ss, o);
        if ((tid & 31) == 0) red[tid >> 5] = ss;
        __syncthreads();
        float tot = red[0] + red[1] + red[2] + red[3];
        __syncthreads();
        float r = rsqrtf(tot * (1.f / DH) + 1e-6f);
        float y = hv * r;
        float lr = g_LR[(size_t)bh * NSEQ + c * CHK + t];
        float dp = (2.f / DH) * (y * gd + g_K[off] - g_V[off]) * lr;
        dg += dp * y;
        float dy = dp * gd;
        float dd = dy * hv;
#pragma unroll
        for (int o = 16; o; o >>= 1) dd += __shfl_xor_sync(~0u, dd, o);
        if ((tid & 31) == 0) red[tid >> 5] = dd;
        __syncthreads();
        float dot = red[0] + red[1] + red[2] + red[3];
        __syncthreads();
        g_DHb[off] = r * dy - (r * r * r * (1.f / DH)) * hv * dot;
    }
    g_SG[(size_t)chunk * DH + tid] = -dg;
}

// dst = scl*op(A)@op(B) (+ascl*add), all 64x64 padded smem (round-13 version)
template<bool TA, bool TB>
__device__ __forceinline__ void mm64(float* dst, const float* A, const float* B,
                                     float scl, const float* add, float ascl,
                                     int tx, int ty) {
    __syncthreads();
    float acc[4][4] = {};
#pragma unroll 4
    for (int k = 0; k < 64; k++) {
        float ra[4], rb[4];
#pragma unroll
        for (int i = 0; i < 4; i++) ra[i] = TA ? A[k * SP + ty * 4 + i] : A[(ty * 4 + i) * SP + k];
#pragma unroll
        for (int j = 0; j < 4; j++) rb[j] = TB ? B[(tx + 16 * j) * SP + k] : B[k * SP + tx + 16 * j];
#pragma unroll
        for (int i = 0; i < 4; i++)
#pragma unroll
            for (int j = 0; j < 4; j++) acc[i][j] += ra[i] * rb[j];
    }
#pragma unroll
    for (int i = 0; i < 4; i++)
#pragma unroll
        for (int j = 0; j < 4; j++) {
            float v = scl * acc[i][j];
            if (add) v = fmaf(ascl, add[(ty * 4 + i) * SP + tx + 16 * j], v);
            dst[(ty * 4 + i) * SP + tx + 16 * j] = v;
        }
}

// ---- Gram-space NS (round-13 fp32 version): 99.8KB smem, 2 blocks/SM -------
__global__ void __launch_bounds__(256) k_nsg() {
    extern __shared__ float sm[];
    float* P  = sm;          float* Q  = sm + NB;
    float* T1 = sm + 2 * NB; float* T2 = sm + 3 * NB;
    float* Mb = sm + 4 * NB; float* M2 = sm + 5 * NB;
    __shared__ float red[9];
    int mat = blockIdx.x;
    bool w2 = mat >= 256;
    int ch = w2 ? mat - 256 : mat;
    size_t rowBase = (size_t)(ch / NC) * NSEQ + (size_t)(ch % NC) * CHK;
    const float* Ag = (w2 ? g_DHb : g_K) + rowBase * DH;
    const float* Bg = (w2 ? g_GE : g_DZ) + rowBase * HID;
    float* Gout = (w2 ? g_G2 : g_G1) + (size_t)ch * MAT1;
    int tid = threadIdx.x, tx = tid & 15, ty = tid >> 4;
    float* As = T1;  // spans T1,T2 (128 x SP)

#pragma unroll
    for (int p = 0; p < 32; p++) { int idx = tid + p * 256; int i = idx & 127, t = idx >> 7;
        As[i * SP + t] = Ag[(size_t)t * DH + i]; }
    __syncthreads();
    {   // P = A A^T
        float acc[4][4] = {};
#pragma unroll 4
        for (int k = 0; k < 128; k++) {
            float ra[4], rb[4];
#pragma unroll
            for (int i = 0; i < 4; i++) ra[i] = As[k * SP + ty * 4 + i];
#pragma unroll
            for (int j = 0; j < 4; j++) rb[j] = As[k * SP + tx + 16 * j];
#pragma unroll
            for (int i = 0; i < 4; i++)
#pragma unroll
                for (int j = 0; j < 4; j++) acc[i][j] += ra[i] * rb[j];
        }
#pragma unroll
        for (int i = 0; i < 4; i++)
#pragma unroll
            for (int j = 0; j < 4; j++) P[(ty * 4 + i) * SP + tx + 16 * j] = acc[i][j];
    }
    {   // Q = B B^T, 8 panels through M2
        float qacc[4][4] = {};
        for (int p = 0; p < 8; p++) {
            __syncthreads();
#pragma unroll
            for (int q = 0; q < 16; q++) { int idx = tid + q * 256; int jl = idx & 63, u = idx >> 6;
                M2[jl * SP + u] = Bg[(size_t)u * HID + p * 64 + jl]; }
            __syncthreads();
#pragma unroll 4
            for (int k = 0; k < 64; k++) {
                float ra[4], rb[4];
#pragma unroll
                for (int i = 0; i < 4; i++) ra[i] = M2[k * SP + ty * 4 + i];
#pragma unroll
                for (int j = 0; j < 4; j++) rb[j] = M2[k * SP + tx + 16 * j];
#pragma unroll
                for (int i = 0; i < 4; i++)
#pragma unroll
                    for (int j = 0; j < 4; j++) qacc[i][j] += ra[i] * rb[j];
            }
        }
        __syncthreads();
#pragma unroll
        for (int i = 0; i < 4; i++)
#pragma unroll
            for (int j = 0; j < 4; j++) Q[(ty * 4 + i) * SP + tx + 16 * j] = qacc[i][j];
    }
    __syncthreads();
    {   // 1/||t||_F = rsqrt(tr(PQ))
        float tsum = 0.f;
#pragma unroll
        for (int q = 0; q < 16; q++) { int idx = tid + q * 256; int t = idx >> 6, u = idx & 63;
            tsum += P[t * SP + u] * Q[t * SP + u]; }
#pragma unroll
        for (int o = 16; o; o >>= 1) tsum += __shfl_xor_sync(~0u, tsum, o);
        if ((tid & 31) == 0) red[tid >> 5] = tsum;
        __syncthreads();
        if (tid == 0) {
            float tot = 0.f;
#pragma unroll
            for (int i = 0; i < 8; i++) tot += red[i];
            red[8] = 1.f / fmaxf(sqrtf(tot), 1e-7f);
        }
        __syncthreads();
    }
    float s = red[8];
#pragma unroll
    for (int q = 0; q < 16; q++) { int idx = tid + q * 256; int t = idx >> 6, u = idx & 63;
        Mb[t * SP + u] = (t == u) ? -s : 0.f; }

    const float ca = 3.4445f, cb = -4.775f, cc = 2.0315f;
    float *pM = Mb, *pY = M2;
#pragma unroll 1
    for (int it = 0; it < 5; it++) {
        mm64<true , false>(T1, pM, P,  1.f, nullptr, 0.f, tx, ty);
        mm64<false, false>(T2, T1, pM, 1.f, nullptr, 0.f, tx, ty);
        mm64<false, false>(T1, Q,  T2, 1.f, nullptr, 0.f, tx, ty);
        mm64<false, false>(T2, T1, T1, cc,  T1, cb, tx, ty);
        mm64<false, false>(pY, pM, T2, 1.f, pM, ca, tx, ty);
        float* tmp = pM; pM = pY; pY = tmp;
    }
    __syncthreads();
#pragma unroll
    for (int p = 0; p < 32; p++) { int idx = tid + p * 256; int i = idx & 127, t = idx >> 7;
        As[i * SP + t] = Ag[(size_t)t * DH + i]; }
    __syncthreads();
    float* sR = P;  // spans P,Q
    {   // R = A^T M
        float acc[8][4] = {};
#pragma unroll 2
        for (int t = 0; t < 64; t++) {
            float ra[8], rb[4];
#pragma unroll
            for (int i = 0; i < 8; i++) ra[i] = As[(ty * 8 + i) * SP + t];
#pragma unroll
            for (int j = 0; j < 4; j++) rb[j] = pM[t * SP + tx + 16 * j];
#pragma unroll
            for (int i = 0; i < 8; i++)
#pragma unroll
                for (int j = 0; j < 4; j++) acc[i][j] += ra[i] * rb[j];
        }
#pragma unroll
        for (int i = 0; i < 8; i++)
#pragma unroll
            for (int j = 0; j < 4; j++) sR[(ty * 8 + i) * SP + tx + 16 * j] = acc[i][j];
    }
    float* bounce = T2;
    for (int p = 0; p < 8; p++) {
        __syncthreads();
#pragma unroll
        for (int q = 0; q < 16; q++) { int idx = tid + q * 256; int jl = idx & 63, u = idx >> 6;
            T1[u * SP + jl] = Bg[(size_t)u * HID + p * 64 + jl]; }
        __syncthreads();
        float acc[8][4] = {};
#pragma unroll 2
        for (int u = 0; u < 64; u++) {
            float ra[8], rb[4];
#pragma unroll
            for (int i = 0; i < 8; i++) ra[i] = sR[(ty * 8 + i) * SP + u];
#pragma unroll
            for (int j = 0; j < 4; j++) rb[j] = T1[u * SP + tx + 16 * j];
#pragma unroll
            for (int i = 0; i < 8; i++)
#pragma unroll
                for (int j = 0; j < 4; j++) acc[i][j] += ra[i] * rb[j];
        }
        if (!w2) {
#pragma unroll
            for (int i = 0; i < 8; i++)
#pragma unroll
                for (int j = 0; j < 4; j++)
                    Gout[(size_t)(ty * 8 + i) * HID + p * 64 + tx + 16 * j] = acc[i][j];
        } else {
            __syncthreads();
#pragma unroll
            for (int i = 0; i < 8; i++)
#pragma unroll
                for (int j = 0; j < 4; j++)
                    bounce[(tx + 16 * j) * 130 + ty * 8 + i] = acc[i][j];
            __syncthreads();
#pragma unroll
            for (int q = 0; q < 32; q++) { int idx = tid + q * 256; int i = idx & 127, jl = idx >> 7;
                Gout[(size_t)(p * 64 + jl) * DH + i] = bounce[jl * 130 + i]; }
        }
    }
}

__global__ void k_scan(const float* __restrict__ S, const float* __restrict__ init,
                       float* __restrict__ R, int matSize) {
    size_t e = (size_t)blockIdx.x * blockDim.x + threadIdx.x;
    if (e >= (size_t)BH * matSize) return;
    int bh = (int)(e / matSize); size_t off = e % matSize;
    float m = 0.f, w = init[(size_t)(bh % NH) * matSize + off];
    const float* mom = g_MOM + (size_t)bh * NC;
    const float* dec = g_DEC + (size_t)bh * NC;
    for (int c = 0; c < NC; c++) {
        size_t idx = ((size_t)bh * NC + c) * matSize + off;
        m = mom[c] * m + S[idx];
        R[idx] = w;
        w = (1.f - dec[c]) * w + m;
    }
}

// ---- retrieval epilogue: rmsnorm(scanned gamma) + q residual + gate --------
__global__ void k_retepi() {
    int chunk = blockIdx.x;               // bh*NC + c
    int bh = chunk / NC, c = chunk % NC;
    int tid = threadIdx.x;                // 128 = dh
    __shared__ float red[4];
    const float* O2 = g_HM + (size_t)chunk * (CHK * DH);
    const float* Qp = g_Q + ((size_t)bh * NSEQ + c * CHK) * DH;
    float gd = g_RG[(size_t)chunk * DH + tid];
    int b = bh / NH, h = bh % NH;
    for (int t = 0; t < CHK; t++) {
        float v = O2[t * DH + tid];
        float ss = v * v;
#pragma unroll
        for (int o = 16; o; o >>= 1) ss += __shfl_xor_sync(~0u, ss, o);
        if ((tid & 31) == 0) red[tid >> 5] = ss;
        __syncthreads();
        float tot = red[0] + red[1] + red[2] + red[3];
        __syncthreads();
        float r = rsqrtf(tot * (1.f / DH) + 1e-6f);
        float out = v * r * gd + Qp[t * DH + tid];
        float gate = g_GATE[(size_t)bh * NSEQ + c * CHK + t];
        g_O[((size_t)b * NSEQ + c * CHK + t) * DIM + h * DH + tid] = out * gate;
    }
}

} // namespace

extern "C" void kernel_launch(void* const* d_in, const int* in_sizes, int n_in,
                              void* d_out, int out_size) {
    const float* seq   = (const float*)d_in[0];
    const float* sg    = (const float*)d_in[1];
    const float* rg    = (const float*)d_in[2];
    const float* Wq    = (const float*)d_in[3];
    const float* Wk    = (const float*)d_in[4];
    const float* Wv    = (const float*)d_in[5];
    const float* Wlr   = (const float*)d_in[6];
    const float* blr   = (const float*)d_in[7];
    const float* Wm    = (const float*)d_in[8];
    const float* bm    = (const float*)d_in[9];
    const float* Wd    = (const float*)d_in[10];
    const float* bd    = (const float*)d_in[11];
    const float* Wgate = (const float*)d_in[12];
    const float* Wc    = (const float*)d_in[13];
    const float* mw1   = (const float*)d_in[14];
    const float* mw2   = (const float*)d_in[15];
    const float* mgam  = (const float*)d_in[16];
    float* out = (float*)d_out;

    const int NSG_SMEM = 6 * NB * 4;   // 99,840 B
    cudaFuncSetAttribute(k_nsg, cudaFuncAttributeMaxDynamicSharedMemorySize, NSG_SMEM);

    float *pG1, *pG2, *pR1, *pR2, *pSG, *pRG, *pK, *pGE, *pDZ, *pDHb;
    float *pS, *pSR, *pO, *pV, *pQ, *pZ, *pHM, *pW2T;
    cudaGetSymbolAddress((void**)&pG1, g_G1);
    cudaGetSymbolAddress((void**)&pG2, g_G2);
    cudaGetSymbolAddress((void**)&pR1, g_R1);
    cudaGetSymbolAddress((void**)&pR2, g_R2);
    cudaGetSymbolAddress((void**)&pSG, g_SG);
    cudaGetSymbolAddress((void**)&pRG, g_RG);
    cudaGetSymbolAddress((void**)&pK,  g_K);
    cudaGetSymbolAddress((void**)&pGE, g_GE);
    cudaGetSymbolAddress((void**)&pDZ, g_DZ);
    cudaGetSymbolAddress((void**)&pDHb,g_DHb);
    cudaGetSymbolAddress((void**)&pS,  g_S);
    cudaGetSymbolAddress((void**)&pSR, g_SR);
    cudaGetSymbolAddress((void**)&pO,  g_O);
    cudaGetSymbolAddress((void**)&pV,  g_V);
    cudaGetSymbolAddress((void**)&pQ,  g_Q);
    cudaGetSymbolAddress((void**)&pZ,  g_Z);
    cudaGetSymbolAddress((void**)&pHM, g_HM);
    cudaGetSymbolAddress((void**)&pW2T,g_W2T);

    k_rmsnorm<<<BN, 128>>>(seq, sg, rg);
    k_pool<<<(BB * NC * DIM + 255) / 256, 256>>>();
    k_lrgate<<<BN, 128>>>(Wlr, blr, Wgate);
    k_momdec<<<BB * NC, 128>>>(Wm, bm, Wd, bd);
    k_w2t<<<(NH * HID * DH + 255) / 256, 256>>>(mw2);

    unsigned long long ND = (unsigned long long)NSEQ * DH;
    unsigned long long NHd = (unsigned long long)NSEQ * HID;
    dim3 gp(64, 8, 1);
    k_tgemm<<<gp, 128>>>(pS,  Wk, pK, nullptr, nullptr, 512, 512, 512, 0, 0, 0, 0, 0, 1);
    k_tgemm<<<gp, 128>>>(pS,  Wv, pV, nullptr, nullptr, 512, 512, 512, 0, 0, 0, 0, 0, 1);
    k_tgemm<<<gp, 128>>>(pSR, Wq, pQ, nullptr, nullptr, 512, 512, 512, 0, 0, 0, 0, 0, 1);

    dim3 gz(32, 8, 8);
    k_tgemm<<<gz, 128>>>(pK, mw1, pZ, pGE, nullptr, 128, 128, 512, 512, ND, MAT1, NHd, 1, 2);
    dim3 gh(32, 2, 8);
    k_tgemm<<<gh, 128>>>(pGE, mw2, pHM, nullptr, nullptr, 512, 512, 128, 128, NHd, MAT1, ND, 1, 0);

    k_backelem<<<BH * NC, 128>>>(mgam);

    k_tgemm<<<gz, 128>>>(pDHb, pW2T, pDZ, nullptr, pZ, 128, 128, 512, 512,
                         ND, (unsigned long long)HID * DH, NHd, 1, 3);

    k_nsg<<<512, 256, NSG_SMEM>>>();

    k_scan<<<(BH * MAT1 + 255) / 256, 256>>>(pG1, mw1, pR1, MAT1);
    k_scan<<<(BH * MAT1 + 255) / 256, 256>>>(pG2, mw2, pR2, MAT1);
    k_scan<<<(BH * DH + 255) / 256, 256>>>(pSG, mgam, pRG, DH);

    // retrieval: Z2 = gelu(Q_chunk @ R1_chunk), batched over 256 chunks
    k_tgemm<<<dim3(1, 8, 256), 128>>>(pQ, pR1, pZ, nullptr, nullptr,
                                      128, 128, 512, 512,
                                      (unsigned long long)(CHK * DH), MAT1,
                                      (unsigned long long)(CHK * HID), 0, 4);
    // O2 = Z2 @ R2_chunk
    k_tgemm<<<dim3(1, 2, 256), 128>>>(pZ, pR2, pHM, nullptr, nullptr,
                                      512, 512, 128, 128,
                                      (unsigned long long)(CHK * HID), MAT1,
                                      (unsigned long long)(CHK * DH), 0, 0);
    k_retepi<<<BH * NC, 128>>>();

    k_tgemm<<<gp, 128>>>(pO, Wc, out, nullptr, nullptr, 512, 512, 512, 512, 0, 0, 0, 0, 0);
}

// round 17
// speedup vs baseline: 1.7234x; 1.2277x over previous
#include <cuda_runtime.h>
#include <cuda_bf16.h>
#include <cmath>
#include <cstdint>

namespace {

constexpr int BB = 2, NSEQ = 2048, DIM = 512, NH = 4, DH = 128, HID = 512;
constexpr int CHK = 64, NC = 32, BH = BB * NH, BN = BB * NSEQ;
constexpr int MAT1 = DH * HID;
constexpr int PL = 64 * 72;       // bf16 elems per plane (64 rows, stride 72)
constexpr int MSLOT = 2 * PL;     // hi+lo planes per matrix slot

__device__ float g_S  [BN * DIM];
__device__ float g_SR [BN * DIM];
__device__ float g_K  [BH * NSEQ * DH];
__device__ float g_V  [BH * NSEQ * DH];
__device__ float g_Q  [BH * NSEQ * DH];
__device__ float g_LR [BH * NSEQ];
__device__ float g_GATE[BH * NSEQ];
__device__ float g_POOL[BB * NC * DIM];
__device__ float g_MOM[BH * NC];
__device__ float g_DEC[BH * NC];
__device__ float g_Z  [BH * NSEQ * HID];   // reused as Z2 in retrieval
__device__ float g_GE [BH * NSEQ * HID];
__device__ float g_HM [BH * NSEQ * DH];    // reused as retrieval MLP out
__device__ float g_DHb[BH * NSEQ * DH];
__device__ float g_DZ [BH * NSEQ * HID];
__device__ float g_W2T[NH * HID * DH];
__device__ float g_G1 [(size_t)BH * NC * MAT1];
__device__ float g_G2 [(size_t)BH * NC * MAT1];
__device__ float g_R1 [(size_t)BH * NC * MAT1];
__device__ float g_R2 [(size_t)BH * NC * MAT1];
__device__ float g_SG [BH * NC * DH];
__device__ float g_RG [BH * NC * DH];
__device__ float g_O  [BN * DIM];

__device__ __forceinline__ float sigm(float x) { return 1.f / (1.f + expf(-x)); }
__device__ __forceinline__ float geluf(float x) {
    return 0.5f * x * (1.f + erff(x * 0.70710678118654752f));
}
__device__ __forceinline__ float dgeluf(float x) {
    return 0.5f * (1.f + erff(x * 0.70710678118654752f))
         + x * 0.3989422804014327f * expf(-0.5f * x * x);
}
__device__ __forceinline__ void mmabf(float* c, const uint32_t* a, const uint32_t* b) {
    asm volatile("mma.sync.aligned.m16n8k16.row.col.f32.bf16.bf16.f32 "
                 "{%0,%1,%2,%3},{%4,%5,%6,%7},{%8,%9},{%0,%1,%2,%3};"
                 : "+f"(c[0]), "+f"(c[1]), "+f"(c[2]), "+f"(c[3])
                 : "r"(a[0]), "r"(a[1]), "r"(a[2]), "r"(a[3]), "r"(b[0]), "r"(b[1]));
}
__device__ __forceinline__ void bfsplit(float v, __nv_bfloat16& h, __nv_bfloat16& l) {
    h = __float2bfloat16(v);
    l = __float2bfloat16(v - __bfloat162float(h));
}
__device__ __forceinline__ float bfjoin(const __nv_bfloat16* p, int idx) {
    return __bfloat162float(p[idx]) + __bfloat162float(p[PL + idx]);
}

// -------------------- rmsnorm of seq with both gains -----------------------
__global__ void k_rmsnorm(const float* __restrict__ seq, const float* __restrict__ sg,
                          const float* __restrict__ rg) {
    int row = blockIdx.x, tid = threadIdx.x;
    const float* x = seq + (size_t)row * DIM;
    float v[4]; float ss = 0.f;
#pragma unroll
    for (int i = 0; i < 4; i++) { v[i] = x[tid + i * 128]; ss += v[i] * v[i]; }
    __shared__ float red[4];
#pragma unroll
    for (int o = 16; o; o >>= 1) ss += __shfl_xor_sync(~0u, ss, o);
    if ((tid & 31) == 0) red[tid >> 5] = ss;
    __syncthreads();
    float r = rsqrtf((red[0] + red[1] + red[2] + red[3]) * (1.f / DIM) + 1e-6f);
#pragma unroll
    for (int i = 0; i < 4; i++) {
        int d = tid + i * 128; float y = v[i] * r;
        g_S [(size_t)row * DIM + d] = y * sg[d];
        g_SR[(size_t)row * DIM + d] = y * rg[d];
    }
}

__global__ void k_pool() {
    int idx = blockIdx.x * blockDim.x + threadIdx.x;
    if (idx >= BB * NC * DIM) return;
    int d = idx % DIM; int bc = idx / DIM;
    size_t base = ((size_t)((bc / NC) * NSEQ + (bc % NC) * CHK)) * DIM + d;
    float a = 0.f;
#pragma unroll 4
    for (int t = 0; t < CHK; t++) a += g_S[base + (size_t)t * DIM];
    g_POOL[idx] = a * (1.f / CHK);
}

__global__ void k_lrgate(const float* __restrict__ Wlr, const float* __restrict__ blr,
                         const float* __restrict__ Wg) {
    int row = blockIdx.x, tid = threadIdx.x;
    float aL[4] = {0,0,0,0}, aG[4] = {0,0,0,0};
    for (int d = tid; d < DIM; d += 128) {
        float sv = g_S[(size_t)row * DIM + d], rv = g_SR[(size_t)row * DIM + d];
#pragma unroll
        for (int h = 0; h < 4; h++) { aL[h] += sv * Wlr[d*4+h]; aG[h] += rv * Wg[d*4+h]; }
    }
    __shared__ float red[32];
#pragma unroll
    for (int h = 0; h < 4; h++) {
        float a = aL[h], g = aG[h];
#pragma unroll
        for (int o = 16; o; o >>= 1) { a += __shfl_xor_sync(~0u, a, o); g += __shfl_xor_sync(~0u, g, o); }
        if ((tid & 31) == 0) { red[h*4 + (tid>>5)] = a; red[16 + h*4 + (tid>>5)] = g; }
    }
    __syncthreads();
    if (tid < 8) {
        int h = tid & 3; bool isG = tid >= 4;
        int base = (isG ? 16 : 0) + h * 4;
        float s = red[base] + red[base+1] + red[base+2] + red[base+3];
        int b = row / NSEQ, tk = row % NSEQ;
        if (!isG) g_LR  [(size_t)(b*NH + h) * NSEQ + tk] = sigm(s + blr[h]);
        else      g_GATE[(size_t)(b*NH + h) * NSEQ + tk] = sigm(s);
    }
}

__global__ void k_momdec(const float* __restrict__ Wm, const float* __restrict__ bm,
                         const float* __restrict__ Wd, const float* __restrict__ bd) {
    int row = blockIdx.x, tid = threadIdx.x;
    float am[4] = {0,0,0,0}, ad[4] = {0,0,0,0};
    for (int d = tid; d < DIM; d += 128) {
        float p = g_POOL[(size_t)row * DIM + d];
#pragma unroll
        for (int h = 0; h < 4; h++) { am[h] += p * Wm[d*4+h]; ad[h] += p * Wd[d*4+h]; }
    }
    __shared__ float red[32];
#pragma unroll
    for (int h = 0; h < 4; h++) {
        float a = am[h], g = ad[h];
#pragma unroll
        for (int o = 16; o; o >>= 1) { a += __shfl_xor_sync(~0u, a, o); g += __shfl_xor_sync(~0u, g, o); }
        if ((tid & 31) == 0) { red[h*4 + (tid>>5)] = a; red[16 + h*4 + (tid>>5)] = g; }
    }
    __syncthreads();
    if (tid < 8) {
        int h = tid & 3; bool isD = tid >= 4;
        int base = (isD ? 16 : 0) + h * 4;
        float s = red[base] + red[base+1] + red[base+2] + red[base+3];
        int b = row / NC, c = row % NC;
        if (!isD) g_MOM[(size_t)(b*NH + h) * NC + c] = sigm(s + bm[h]);
        else      g_DEC[(size_t)(b*NH + h) * NC + c] = sigm(s + bd[h]);
    }
}

__global__ void k_w2t(const float* __restrict__ mw2) {
    int idx = blockIdx.x * blockDim.x + threadIdx.x;
    if (idx >= NH * HID * DH) return;
    int h = idx >> 16, k = (idx & 65535) >> 9, n = idx & 511;
    g_W2T[idx] = mw2[(size_t)h * 65536 + (size_t)n * 128 + k];
}

// ---------- tensor-core GEMM, bf16 hi/lo split. Tile 64x64, BK=32, 128 thr --
// modes: 0 plain; 1 head-scatter; 2 store Z + gelu(Z); 3 *dgelu(Zs); 4 gelu only.
__global__ void __launch_bounds__(128) k_tgemm(
        const float* __restrict__ A, const float* __restrict__ B,
        float* __restrict__ C, float* __restrict__ C2, const float* __restrict__ Zs,
        int K, int lda, int ldb, int ldc,
        unsigned long long aB, unsigned long long bB, unsigned long long cB,
        int bPerHead, int mode) {
    __shared__ __nv_bfloat16 Ah[64 * 40], Al[64 * 40], Bh[64 * 40], Bl[64 * 40];
    int bz = blockIdx.z;
    const float* Ab = A + (size_t)bz * aB;
    const float* Bb = B + (size_t)(bPerHead ? (bz % NH) : bz) * bB;
    float* Cb = C + (size_t)bz * cB;
    float* C2b = C2 ? C2 + (size_t)bz * cB : nullptr;
    const float* Zb = Zs ? Zs + (size_t)bz * cB : nullptr;
    int m0 = blockIdx.x * 64, n0 = blockIdx.y * 64;
    int tid = threadIdx.x, lane = tid & 31, warp = tid >> 5;
    int wm = warp >> 1, wn = warp & 1, gid = lane >> 2, tig = lane & 3;
    float acc[2][4][4] = {};

    for (int kt = 0; kt < K; kt += 32) {
#pragma unroll
        for (int p = 0; p < 4; p++) {
            int q = tid + p * 128; int r = q >> 3, c4 = (q & 7) * 4;
            float4 v = *(const float4*)&Ab[(size_t)(m0 + r) * lda + kt + c4];
            float vv[4] = {v.x, v.y, v.z, v.w};
#pragma unroll
            for (int i = 0; i < 4; i++) {
                __nv_bfloat16 h = __float2bfloat16(vv[i]);
                Ah[r * 40 + c4 + i] = h;
                Al[r * 40 + c4 + i] = __float2bfloat16(vv[i] - __bfloat162float(h));
            }
        }
#pragma unroll
        for (int p = 0; p < 4; p++) {
            int q = tid + p * 128; int r = q >> 4, c4 = (q & 15) * 4;
            float4 v = *(const float4*)&Bb[(size_t)(kt + r) * ldb + n0 + c4];
            float vv[4] = {v.x, v.y, v.z, v.w};
#pragma unroll
            for (int i = 0; i < 4; i++) {
                __nv_bfloat16 h = __float2bfloat16(vv[i]);
                Bh[(c4 + i) * 40 + r] = h;
                Bl[(c4 + i) * 40 + r] = __float2bfloat16(vv[i] - __bfloat162float(h));
            }
        }
        __syncthreads();
#pragma unroll
        for (int ks = 0; ks < 2; ks++) {
            int kb = ks * 16 + 2 * tig;
            uint32_t ah[2][4], al[2][4], bh[4][2], bl[4][2];
#pragma unroll
            for (int mf = 0; mf < 2; mf++) {
                int row = wm * 32 + mf * 16 + gid;
                ah[mf][0] = *(uint32_t*)&Ah[row * 40 + kb];
                ah[mf][1] = *(uint32_t*)&Ah[(row + 8) * 40 + kb];
                ah[mf][2] = *(uint32_t*)&Ah[row * 40 + kb + 8];
                ah[mf][3] = *(uint32_t*)&Ah[(row + 8) * 40 + kb + 8];
                al[mf][0] = *(uint32_t*)&Al[row * 40 + kb];
                al[mf][1] = *(uint32_t*)&Al[(row + 8) * 40 + kb];
                al[mf][2] = *(uint32_t*)&Al[row * 40 + kb + 8];
                al[mf][3] = *(uint32_t*)&Al[(row + 8) * 40 + kb + 8];
            }
#pragma unroll
            for (int nf = 0; nf < 4; nf++) {
                int n = wn * 32 + nf * 8 + gid;
                bh[nf][0] = *(uint32_t*)&Bh[n * 40 + kb];
                bh[nf][1] = *(uint32_t*)&Bh[n * 40 + kb + 8];
                bl[nf][0] = *(uint32_t*)&Bl[n * 40 + kb];
                bl[nf][1] = *(uint32_t*)&Bl[n * 40 + kb + 8];
            }
#pragma unroll
            for (int mf = 0; mf < 2; mf++)
#pragma unroll
                for (int nf = 0; nf < 4; nf++) {
                    mmabf(acc[mf][nf], ah[mf], bh[nf]);
                    mmabf(acc[mf][nf], ah[mf], bl[nf]);
                    mmabf(acc[mf][nf], al[mf], bh[nf]);
                }
        }
        __syncthreads();
    }
#pragma unroll
    for (int mf = 0; mf < 2; mf++)
#pragma unroll
        for (int nf = 0; nf < 4; nf++)
#pragma unroll
            for (int half = 0; half < 2; half++) {
                int row = m0 + wm * 32 + mf * 16 + gid + half * 8;
                int col = n0 + wn * 32 + nf * 8 + 2 * tig;
                float v0 = acc[mf][nf][half * 2], v1 = acc[mf][nf][half * 2 + 1];
                if (mode == 0) {
                    *(float2*)&Cb[(size_t)row * ldc + col] = make_float2(v0, v1);
                } else if (mode == 1) {
                    int b = row >> 11, tk = row & 2047, h = col >> 7, dh = col & 127;
                    *(float2*)&Cb[((size_t)(b * NH + h) * NSEQ + tk) * DH + dh] =
                        make_float2(v0, v1);
                } else if (mode == 2) {
                    size_t o = (size_t)row * ldc + col;
                    *(float2*)&Cb[o]  = make_float2(v0, v1);
                    *(float2*)&C2b[o] = make_float2(geluf(v0), geluf(v1));
                } else if (mode == 3) {
                    size_t o = (size_t)row * ldc + col;
                    float2 z = *(const float2*)&Zb[o];
                    *(float2*)&Cb[o] = make_float2(v0 * dgeluf(z.x), v1 * dgeluf(z.y));
                } else {
                    size_t o = (size_t)row * ldc + col;
                    *(float2*)&Cb[o] = make_float2(geluf(v0), geluf(v1));
                }
            }
}

// ---- rmsnorm-backward per chunk token; also -dgamma ------------------------
__global__ void k_backelem(const float* __restrict__ mgamma) {
    int chunk = blockIdx.x;
    int bh = chunk / NC, c = chunk % NC, h = bh % NH;
    int tid = threadIdx.x;
    float gd = mgamma[h * DH + tid];
    __shared__ float red[4];
    float dg = 0.f;
    size_t rowBase = ((size_t)bh * NSEQ + c * CHK) * DH;
    for (int t = 0; t < CHK; t++) {
        size_t off = rowBase + (size_t)t * DH + tid;
        float hv = g_HM[off];
        float ss = hv * hv;
#pragma unroll
        for (int o = 16; o; o >>= 1) ss += __shfl_xor_sync(~0u, ss, o);
        if ((tid & 31) == 0) red[tid >> 5] = ss;
        __syncthreads();
        float tot = red[0] + red[1] + red[2] + red[3];
        __syncthreads();
        float r = rsqrtf(tot * (1.f / DH) + 1e-6f);
        float y = hv * r;
        float lr = g_LR[(size_t)bh * NSEQ + c * CHK + t];
        float dp = (2.f / DH) * (y * gd + g_K[off] - g_V[off]) * lr;
        dg += dp * y;
        float dy = dp * gd;
        float dd = dy * hv;
#pragma unroll
        for (int o = 16; o; o >>= 1) dd += __shfl_xor_sync(~0u, dd, o);
        if ((tid & 31) == 0) red[tid >> 5] = dd;
        __syncthreads();
        float dot = red[0] + red[1] + red[2] + red[3];
        __syncthreads();
        g_DHb[off] = r * dy - (r * r * r * (1.f / DH)) * hv * dot;
    }
    g_SG[(size_t)chunk * DH + tid] = -dg;
}

// ---- NS helpers: 64x64 MMA on bf16 hi/lo smem planes (stride 72) ----------
// Ar: row-major storage of A-op; Bc: storage where [n][k] = Bop[k][n].
__device__ __forceinline__ void mm_acc(const __nv_bfloat16* Ar, const __nv_bfloat16* Bc,
                                       float acc[2][4], int wm, int wn, int gid, int tig) {
    const uint32_t* A32h = (const uint32_t*)Ar;
    const uint32_t* A32l = (const uint32_t*)(Ar + PL);
    const uint32_t* B32h = (const uint32_t*)Bc;
    const uint32_t* B32l = (const uint32_t*)(Bc + PL);
    int ar = wm * 16 + gid;
#pragma unroll
    for (int ks = 0; ks < 4; ks++) {
        int kw = ks * 8 + tig;
        uint32_t ah[4], al[4];
        ah[0] = A32h[ar*36+kw];     ah[1] = A32h[(ar+8)*36+kw];
        ah[2] = A32h[ar*36+kw+4];   ah[3] = A32h[(ar+8)*36+kw+4];
        al[0] = A32l[ar*36+kw];     al[1] = A32l[(ar+8)*36+kw];
        al[2] = A32l[ar*36+kw+4];   al[3] = A32l[(ar+8)*36+kw+4];
#pragma unroll
        for (int nf = 0; nf < 2; nf++) {
            int n = wn * 16 + nf * 8 + gid;
            uint32_t bh[2], bl[2];
            bh[0] = B32h[n*36+kw]; bh[1] = B32h[n*36+kw+4];
            bl[0] = B32l[n*36+kw]; bl[1] = B32l[n*36+kw+4];
            mmabf(acc[nf], ah, bh);
            mmabf(acc[nf], ah, bl);
            mmabf(acc[nf], al, bh);
        }
    }
}
__device__ __forceinline__ void store_rc(float acc[2][4],
                                         __nv_bfloat16* dR, __nv_bfloat16* dC,
                                         float scl, const __nv_bfloat16* addR, float ascl,
                                         int wm, int wn, int gid, int tig) {
#pragma unroll
    for (int nf = 0; nf < 2; nf++)
#pragma unroll
        for (int h = 0; h < 2; h++) {
            int row = wm * 16 + gid + h * 8;
            int col = wn * 16 + nf * 8 + 2 * tig;
            float v0 = scl * acc[nf][h*2], v1 = scl * acc[nf][h*2+1];
            if (addR) {
                v0 += ascl * bfjoin(addR, row*72+col);
                v1 += ascl * bfjoin(addR, row*72+col+1);
            }
            __nv_bfloat16 h0, l0, h1, l1;
            bfsplit(v0, h0, l0); bfsplit(v1, h1, l1);
            if (dR) {
                __nv_bfloat162 hv; hv.x = h0; hv.y = h1;
                __nv_bfloat162 lv; lv.x = l0; lv.y = l1;
                *(__nv_bfloat162*)&dR[row*72+col] = hv;
                *(__nv_bfloat162*)&dR[PL+row*72+col] = lv;
            }
            if (dC) {
                dC[col*72+row] = h0;      dC[(col+1)*72+row] = h1;
                dC[PL+col*72+row] = l0;   dC[PL+(col+1)*72+row] = l1;
            }
        }
}

// ---- Gram-space NS, bf16 hi/lo tensor cores. 165.9KB smem, 512 thr --------
__global__ void __launch_bounds__(512) k_nsg() {
    extern __shared__ __nv_bfloat16 sb[];
    __shared__ float red[17];
    int mat = blockIdx.x;
    bool w2 = mat >= 256;
    int ch = w2 ? mat - 256 : mat;
    size_t rowBase = (size_t)(ch / NC) * NSEQ + (size_t)(ch % NC) * CHK;
    const float* Ag = (w2 ? g_DHb : g_K) + rowBase * DH;
    const float* Bg = (w2 ? g_GE : g_DZ) + rowBase * HID;
    float* Gout = (w2 ? g_G2 : g_G1) + (size_t)ch * MAT1;
    int tid = threadIdx.x, lane = tid & 31, warp = tid >> 5;
    int wm = warp >> 2, wn = warp & 3, gid = lane >> 2, tig = lane & 3;
    __nv_bfloat16 *Ma_r = sb,            *Ma_t = sb + MSLOT;
    __nv_bfloat16 *Mb_r = sb + 2*MSLOT,  *Mb_t = sb + 3*MSLOT;
    __nv_bfloat16 *P    = sb + 4*MSLOT,  *Qm   = sb + 5*MSLOT;
    __nv_bfloat16 *t1   = sb + 6*MSLOT,  *t2   = sb + 7*MSLOT, *t3 = sb + 8*MSLOT;

    // P = A A^T over 2 panels (panel staged row-major [t][i] in t3)
    {
        float acc[2][4] = {};
        for (int p = 0; p < 2; p++) {
            __syncthreads();
#pragma unroll
            for (int it = 0; it < 2; it++) {
                int q = tid + it * 512; int r = q >> 4, c4 = (q & 15) * 4;
                float4 v = *(const float4*)&Ag[(size_t)r * DH + p * 64 + c4];
                __nv_bfloat16 h0,l0,h1,l1,h2,l2,h3,l3;
                bfsplit(v.x,h0,l0); bfsplit(v.y,h1,l1); bfsplit(v.z,h2,l2); bfsplit(v.w,h3,l3);
                __nv_bfloat162 a,b,c,d; a.x=h0;a.y=h1;b.x=h2;b.y=h3;c.x=l0;c.y=l1;d.x=l2;d.y=l3;
                *(__nv_bfloat162*)&t3[r*72+c4] = a;      *(__nv_bfloat162*)&t3[r*72+c4+2] = b;
                *(__nv_bfloat162*)&t3[PL+r*72+c4] = c;   *(__nv_bfloat162*)&t3[PL+r*72+c4+2] = d;
            }
            __syncthreads();
            mm_acc(t3, t3, acc, wm, wn, gid, tig);
        }
        store_rc(acc, P, nullptr, 1.f, nullptr, 0.f, wm, wn, gid, tig);
    }
    // Q = B B^T over 8 panels
    {
        float acc[2][4] = {};
        for (int p = 0; p < 8; p++) {
            __syncthreads();
#pragma unroll
            for (int it = 0; it < 2; it++) {
                int q = tid + it * 512; int r = q >> 4, c4 = (q & 15) * 4;
                float4 v = *(const float4*)&Bg[(size_t)r * HID + p * 64 + c4];
                __nv_bfloat16 h0,l0,h1,l1,h2,l2,h3,l3;
                bfsplit(v.x,h0,l0); bfsplit(v.y,h1,l1); bfsplit(v.z,h2,l2); bfsplit(v.w,h3,l3);
                __nv_bfloat162 a,b,c,d; a.x=h0;a.y=h1;b.x=h2;b.y=h3;c.x=l0;c.y=l1;d.x=l2;d.y=l3;
                *(__nv_bfloat162*)&t3[r*72+c4] = a;      *(__nv_bfloat162*)&t3[r*72+c4+2] = b;
                *(__nv_bfloat162*)&t3[PL+r*72+c4] = c;   *(__nv_bfloat162*)&t3[PL+r*72+c4+2] = d;
            }
            __syncthreads();
            mm_acc(t3, t3, acc, wm, wn, gid, tig);
        }
        store_rc(acc, Qm, nullptr, 1.f, nullptr, 0.f, wm, wn, gid, tig);
    }
    __syncthreads();
    // 1/||t||_F = rsqrt(tr(PQ))
    {
        float ts = 0.f;
#pragma unroll
        for (int it = 0; it < 8; it++) {
            int q = tid + it * 512; int t = q >> 6, u = q & 63;
            ts += bfjoin(P, t*72+u) * bfjoin(Qm, t*72+u);
        }
#pragma unroll
        for (int o = 16; o; o >>= 1) ts += __shfl_xor_sync(~0u, ts, o);
        if (lane == 0) red[warp] = ts;
        __syncthreads();
        if (tid == 0) {
            float tot = 0.f;
#pragma unroll
            for (int i = 0; i < 16; i++) tot += red[i];
            red[16] = 1.f / fmaxf(sqrtf(tot), 1e-7f);
        }
        __syncthreads();
    }
    float s = red[16];
    __nv_bfloat16 sh, sl; bfsplit(-s, sh, sl);
    __nv_bfloat16 zb = __float2bfloat16(0.f);
#pragma unroll
    for (int it = 0; it < 8; it++) {
        int q = tid + it * 512; int t = q >> 6, u = q & 63;
        __nv_bfloat16 hv = (t == u) ? sh : zb;
        __nv_bfloat16 lv = (t == u) ? sl : zb;
        Ma_r[t*72+u] = hv; Ma_r[PL+t*72+u] = lv;
        Ma_t[t*72+u] = hv; Ma_t[PL+t*72+u] = lv;
    }
    const float ca = 3.4445f, cb = -4.775f, cc = 2.0315f;
    __nv_bfloat16 *Mr = Ma_r, *Mt = Ma_t, *Yr = Mb_r, *Yt = Mb_t;
#pragma unroll 1
    for (int itn = 0; itn < 5; itn++) {
        { __syncthreads(); float acc[2][4] = {};            // T1 = M^T P
          mm_acc(Mt, P, acc, wm, wn, gid, tig);
          store_rc(acc, t1, nullptr, 1.f, nullptr, 0.f, wm, wn, gid, tig); }
        { __syncthreads(); float acc[2][4] = {};            // T2 = T1 M (col store)
          mm_acc(t1, Mt, acc, wm, wn, gid, tig);
          store_rc(acc, nullptr, t2, 1.f, nullptr, 0.f, wm, wn, gid, tig); }
        { __syncthreads(); float acc[2][4] = {};            // F = Q T2 -> Fr(t1), Fc(t3)
          mm_acc(Qm, t2, acc, wm, wn, gid, tig);
          store_rc(acc, t1, t3, 1.f, nullptr, 0.f, wm, wn, gid, tig); }
        { __syncthreads(); float acc[2][4] = {};            // G = cF^2 + bF (col -> t2)
          mm_acc(t1, t3, acc, wm, wn, gid, tig);
          store_rc(acc, nullptr, t2, cc, t1, cb, wm, wn, gid, tig); }
        { __syncthreads(); float acc[2][4] = {};            // M' = M G + a M
          mm_acc(Mr, t2, acc, wm, wn, gid, tig);
          store_rc(acc, Yr, Yt, 1.f, Mr, ca, wm, wn, gid, tig); }
        __nv_bfloat16* tp;
        tp = Mr; Mr = Yr; Yr = tp;
        tp = Mt; Mt = Yt; Yt = tp;
    }
    // R = A^T M: halves into P, Q slots (At panel staged transposed in t3)
    for (int hf = 0; hf < 2; hf++) {
        __syncthreads();
#pragma unroll
        for (int it = 0; it < 2; it++) {
            int q = tid + it * 512; int r = q >> 4, c4 = (q & 15) * 4;
            float4 v = *(const float4*)&Ag[(size_t)r * DH + hf * 64 + c4];
            __nv_bfloat16 h, l;
            bfsplit(v.x,h,l); t3[(c4+0)*72+r]=h; t3[PL+(c4+0)*72+r]=l;
            bfsplit(v.y,h,l); t3[(c4+1)*72+r]=h; t3[PL+(c4+1)*72+r]=l;
            bfsplit(v.z,h,l); t3[(c4+2)*72+r]=h; t3[PL+(c4+2)*72+r]=l;
            bfsplit(v.w,h,l); t3[(c4+3)*72+r]=h; t3[PL+(c4+3)*72+r]=l;
        }
        __syncthreads();
        float acc[2][4] = {};
        mm_acc(t3, Mt, acc, wm, wn, gid, tig);
        store_rc(acc, hf ? Qm : P, nullptr, 1.f, nullptr, 0.f, wm, wn, gid, tig);
    }
    // out = R @ B over 8 panels (Bt staged transposed in t3); bounce in t1 (fp32)
    float* bounce = (float*)t1;
    for (int p = 0; p < 8; p++) {
        __syncthreads();
#pragma unroll
        for (int it = 0; it < 2; it++) {
            int q = tid + it * 512; int r = q >> 4, c4 = (q & 15) * 4;
            float4 v = *(const float4*)&Bg[(size_t)r * HID + p * 64 + c4];
            __nv_bfloat16 h, l;
            bfsplit(v.x,h,l); t3[(c4+0)*72+r]=h; t3[PL+(c4+0)*72+r]=l;
            bfsplit(v.y,h,l); t3[(c4+1)*72+r]=h; t3[PL+(c4+1)*72+r]=l;
            bfsplit(v.z,h,l); t3[(c4+2)*72+r]=h; t3[PL+(c4+2)*72+r]=l;
            bfsplit(v.w,h,l); t3[(c4+3)*72+r]=h; t3[PL+(c4+3)*72+r]=l;
        }
        __syncthreads();
        for (int hf = 0; hf < 2; hf++) {
            float acc[2][4] = {};
            mm_acc(hf ? Qm : P, t3, acc, wm, wn, gid, tig);
            if (!w2) {
#pragma unroll
                for (int nf = 0; nf < 2; nf++)
#pragma unroll
                    for (int h = 0; h < 2; h++) {
                        int row = wm * 16 + gid + h * 8;
                        int col = wn * 16 + nf * 8 + 2 * tig;
                        *(float2*)&Gout[(size_t)(hf * 64 + row) * HID + p * 64 + col] =
                            make_float2(acc[nf][h*2], acc[nf][h*2+1]);
                    }
            } else {
#pragma unroll
                for (int nf = 0; nf < 2; nf++)
#pragma unroll
                    for (int h = 0; h < 2; h++) {
                        int row = wm * 16 + gid + h * 8;
                        int col = wn * 16 + nf * 8 + 2 * tig;
                        bounce[col * 66 + row] = acc[nf][h*2];
                        bounce[(col + 1) * 66 + row] = acc[nf][h*2+1];
                    }
                __syncthreads();
#pragma unroll
                for (int it = 0; it < 8; it++) {
                    int q = tid + it * 512; int jl = q >> 6, i = q & 63;
                    Gout[(size_t)(p * 64 + jl) * DH + hf * 64 + i] = bounce[jl * 66 + i];
                }
                __syncthreads();
            }
        }
    }
}

__global__ void k_scan(const float* __restrict__ S, const float* __restrict__ init,
                       float* __restrict__ R, int matSize) {
    size_t e = (size_t)blockIdx.x * blockDim.x + threadIdx.x;
    if (e >= (size_t)BH * matSize) return;
    int bh = (int)(e / matSize); size_t off = e % matSize;
    float m = 0.f, w = init[(size_t)(bh % NH) * matSize + off];
    const float* mom = g_MOM + (size_t)bh * NC;
    const float* dec = g_DEC + (size_t)bh * NC;
    for (int c = 0; c < NC; c++) {
        size_t idx = ((size_t)bh * NC + c) * matSize + off;
        m = mom[c] * m + S[idx];
        R[idx] = w;
        w = (1.f - dec[c]) * w + m;
    }
}

// ---- retrieval epilogue: rmsnorm(scanned gamma) + q residual + gate --------
__global__ void k_retepi() {
    int chunk = blockIdx.x;
    int bh = chunk / NC, c = chunk % NC;
    int tid = threadIdx.x;
    __shared__ float red[4];
    const float* O2 = g_HM + (size_t)chunk * (CHK * DH);
    const float* Qp = g_Q + ((size_t)bh * NSEQ + c * CHK) * DH;
    float gd = g_RG[(size_t)chunk * DH + tid];
    int b = bh / NH, h = bh % NH;
    for (int t = 0; t < CHK; t++) {
        float v = O2[t * DH + tid];
        float ss = v * v;
#pragma unroll
        for (int o = 16; o; o >>= 1) ss += __shfl_xor_sync(~0u, ss, o);
        if ((tid & 31) == 0) red[tid >> 5] = ss;
        __syncthreads();
        float tot = red[0] + red[1] + red[2] + red[3];
        __syncthreads();
        float r = rsqrtf(tot * (1.f / DH) + 1e-6f);
        float out = v * r * gd + Qp[t * DH + tid];
        float gate = g_GATE[(size_t)bh * NSEQ + c * CHK + t];
        g_O[((size_t)b * NSEQ + c * CHK + t) * DIM + h * DH + tid] = out * gate;
    }
}

} // namespace

extern "C" void kernel_launch(void* const* d_in, const int* in_sizes, int n_in,
                              void* d_out, int out_size) {
    const float* seq   = (const float*)d_in[0];
    const float* sg    = (const float*)d_in[1];
    const float* rg    = (const float*)d_in[2];
    const float* Wq    = (const float*)d_in[3];
    const float* Wk    = (const float*)d_in[4];
    const float* Wv    = (const float*)d_in[5];
    const float* Wlr   = (const float*)d_in[6];
    const float* blr   = (const float*)d_in[7];
    const float* Wm    = (const float*)d_in[8];
    const float* bm    = (const float*)d_in[9];
    const float* Wd    = (const float*)d_in[10];
    const float* bd    = (const float*)d_in[11];
    const float* Wgate = (const float*)d_in[12];
    const float* Wc    = (const float*)d_in[13];
    const float* mw1   = (const float*)d_in[14];
    const float* mw2   = (const float*)d_in[15];
    const float* mgam  = (const float*)d_in[16];
    float* out = (float*)d_out;

    const int NSG_SMEM = 9 * MSLOT * 2;   // 165,888 B
    cudaFuncSetAttribute(k_nsg, cudaFuncAttributeMaxDynamicSharedMemorySize, NSG_SMEM);

    float *pG1, *pG2, *pR1, *pR2, *pSG, *pRG, *pK, *pGE, *pDZ, *pDHb;
    float *pS, *pSR, *pO, *pV, *pQ, *pZ, *pHM, *pW2T;
    cudaGetSymbolAddress((void**)&pG1, g_G1);
    cudaGetSymbolAddress((void**)&pG2, g_G2);
    cudaGetSymbolAddress((void**)&pR1, g_R1);
    cudaGetSymbolAddress((void**)&pR2, g_R2);
    cudaGetSymbolAddress((void**)&pSG, g_SG);
    cudaGetSymbolAddress((void**)&pRG, g_RG);
    cudaGetSymbolAddress((void**)&pK,  g_K);
    cudaGetSymbolAddress((void**)&pGE, g_GE);
    cudaGetSymbolAddress((void**)&pDZ, g_DZ);
    cudaGetSymbolAddress((void**)&pDHb,g_DHb);
    cudaGetSymbolAddress((void**)&pS,  g_S);
    cudaGetSymbolAddress((void**)&pSR, g_SR);
    cudaGetSymbolAddress((void**)&pO,  g_O);
    cudaGetSymbolAddress((void**)&pV,  g_V);
    cudaGetSymbolAddress((void**)&pQ,  g_Q);
    cudaGetSymbolAddress((void**)&pZ,  g_Z);
    cudaGetSymbolAddress((void**)&pHM, g_HM);
    cudaGetSymbolAddress((void**)&pW2T,g_W2T);

    k_rmsnorm<<<BN, 128>>>(seq, sg, rg);
    k_pool<<<(BB * NC * DIM + 255) / 256, 256>>>();
    k_lrgate<<<BN, 128>>>(Wlr, blr, Wgate);
    k_momdec<<<BB * NC, 128>>>(Wm, bm, Wd, bd);
    k_w2t<<<(NH * HID * DH + 255) / 256, 256>>>(mw2);

    unsigned long long ND = (unsigned long long)NSEQ * DH;
    unsigned long long NHd = (unsigned long long)NSEQ * HID;
    dim3 gp(64, 8, 1);
    k_tgemm<<<gp, 128>>>(pS,  Wk, pK, nullptr, nullptr, 512, 512, 512, 0, 0, 0, 0, 0, 1);
    k_tgemm<<<gp, 128>>>(pS,  Wv, pV, nullptr, nullptr, 512, 512, 512, 0, 0, 0, 0, 0, 1);
    k_tgemm<<<gp, 128>>>(pSR, Wq, pQ, nullptr, nullptr, 512, 512, 512, 0, 0, 0, 0, 0, 1);

    dim3 gz(32, 8, 8);
    k_tgemm<<<gz, 128>>>(pK, mw1, pZ, pGE, nullptr, 128, 128, 512, 512, ND, MAT1, NHd, 1, 2);
    dim3 gh(32, 2, 8);
    k_tgemm<<<gh, 128>>>(pGE, mw2, pHM, nullptr, nullptr, 512, 512, 128, 128, NHd, MAT1, ND, 1, 0);

    k_backelem<<<BH * NC, 128>>>(mgam);

    k_tgemm<<<gz, 128>>>(pDHb, pW2T, pDZ, nullptr, pZ, 128, 128, 512, 512,
                         ND, (unsigned long long)HID * DH, NHd, 1, 3);

    k_nsg<<<512, 512, NSG_SMEM>>>();

    k_scan<<<(BH * MAT1 + 255) / 256, 256>>>(pG1, mw1, pR1, MAT1);
    k_scan<<<(BH * MAT1 + 255) / 256, 256>>>(pG2, mw2, pR2, MAT1);
    k_scan<<<(BH * DH + 255) / 256, 256>>>(pSG, mgam, pRG, DH);

    // retrieval: Z2 = gelu(Q_chunk @ R1_chunk), batched over 256 chunks
    k_tgemm<<<dim3(1, 8, 256), 128>>>(pQ, pR1, pZ, nullptr, nullptr,
                                      128, 128, 512, 512,
                                      (unsigned long long)(CHK * DH), MAT1,
                                      (unsigned long long)(CHK * HID), 0, 4);
    // O2 = Z2 @ R2_chunk
    k_tgemm<<<dim3(1, 2, 256), 128>>>(pZ, pR2, pHM, nullptr, nullptr,
                                      512, 512, 128, 128,
                                      (unsigned long long)(CHK * HID), MAT1,
                                      (unsigned long long)(CHK * DH), 0, 0);
    k_retepi<<<BH * NC, 128>>>();

    k_tgemm<<<gp, 128>>>(pO, Wc, out, nullptr, nullptr, 512, 512, 512, 512, 0, 0, 0, 0, 0);
}